// round 1
// baseline (speedup 1.0000x reference)
#include <cuda_runtime.h>
#include <math.h>

// Problem constants
#define BB   2
#define SS   2048
#define HH   1024
#define NHH  16
#define HDD  64

// Scratch (device globals: allocation-free contract)
__device__ float g_q[BB * SS * HH];
__device__ float g_k[BB * SS * HH];
__device__ float g_v[BB * SS * HH];
__device__ float g_ctx[BB * SS * HH];

// ----------------------------------------------------------------------------
// Dual-weight SGEMM: C[M,N] = A[M,K] @ (Ws + Wd)^T, all fp32.
// Ws/Wd are [N,K] row-major, so B-operand B[k][n] = Ws[n][k] + Wd[n][k].
// 128x128 block tile, BK=8, 256 threads, 8x8 microtile, register prefetch.
// ----------------------------------------------------------------------------
__global__ void __launch_bounds__(256) gemm_dual(
    const float* __restrict__ A,
    const float* __restrict__ Ws,
    const float* __restrict__ Wd,
    float* __restrict__ C,
    int M, int N, int K)
{
    __shared__ float As[8][132];
    __shared__ float Bs[8][132];

    const int tid  = threadIdx.x;
    const int m0   = blockIdx.y * 128;
    const int n0   = blockIdx.x * 128;
    const int lrow = tid >> 1;          // 0..127
    const int lseg = (tid & 1) << 2;    // 0 or 4

    const float* Ap = A  + (size_t)(m0 + lrow) * K + lseg;
    const float* Sp = Ws + (size_t)(n0 + lrow) * K + lseg;
    const float* Dp = Wd + (size_t)(n0 + lrow) * K + lseg;

    const int tx = tid & 15;
    const int ty = tid >> 4;

    float acc[8][8];
#pragma unroll
    for (int i = 0; i < 8; i++)
#pragma unroll
        for (int j = 0; j < 8; j++) acc[i][j] = 0.0f;

    float4 ra = *(const float4*)Ap;
    float4 rs = *(const float4*)Sp;
    float4 rd = *(const float4*)Dp;

    const int ntiles = K >> 3;
    for (int kt = 0; kt < ntiles; ++kt) {
        As[lseg + 0][lrow] = ra.x;
        As[lseg + 1][lrow] = ra.y;
        As[lseg + 2][lrow] = ra.z;
        As[lseg + 3][lrow] = ra.w;
        Bs[lseg + 0][lrow] = rs.x + rd.x;
        Bs[lseg + 1][lrow] = rs.y + rd.y;
        Bs[lseg + 2][lrow] = rs.z + rd.z;
        Bs[lseg + 3][lrow] = rs.w + rd.w;
        __syncthreads();

        if (kt + 1 < ntiles) {
            const int off = (kt + 1) << 3;
            ra = *(const float4*)(Ap + off);
            rs = *(const float4*)(Sp + off);
            rd = *(const float4*)(Dp + off);
        }

#pragma unroll
        for (int kk = 0; kk < 8; ++kk) {
            float4 a0 = *(const float4*)&As[kk][ty * 8];
            float4 a1 = *(const float4*)&As[kk][ty * 8 + 4];
            float4 b0 = *(const float4*)&Bs[kk][tx * 8];
            float4 b1 = *(const float4*)&Bs[kk][tx * 8 + 4];
            float av[8] = {a0.x, a0.y, a0.z, a0.w, a1.x, a1.y, a1.z, a1.w};
            float bv[8] = {b0.x, b0.y, b0.z, b0.w, b1.x, b1.y, b1.z, b1.w};
#pragma unroll
            for (int i = 0; i < 8; i++)
#pragma unroll
                for (int j = 0; j < 8; j++)
                    acc[i][j] = fmaf(av[i], bv[j], acc[i][j]);
        }
        __syncthreads();
    }

#pragma unroll
    for (int i = 0; i < 8; i++) {
        float* cp = C + (size_t)(m0 + ty * 8 + i) * N + n0 + tx * 8;
        *(float4*)(cp)     = make_float4(acc[i][0], acc[i][1], acc[i][2], acc[i][3]);
        *(float4*)(cp + 4) = make_float4(acc[i][4], acc[i][5], acc[i][6], acc[i][7]);
    }
}

// ----------------------------------------------------------------------------
// Flash attention, fp32, online softmax.
// Block: one (b, h, q-tile of 128). 256 threads: ry=tid/8 (row group of 4),
// cx=tid%8 (col group of 8). K-tiles of 64.
// Dynamic smem: QT[64][132] | KT[64][68] | V[64][68] | PT[64][132] = 102400 B
// ----------------------------------------------------------------------------
__global__ void __launch_bounds__(256) attn_kernel(
    const float* __restrict__ Q,
    const float* __restrict__ K,
    const float* __restrict__ V,
    const float* __restrict__ mask,
    float* __restrict__ ctx)
{
    extern __shared__ float sm[];
    float* QT = sm;                    // [64][132] : QT[d][r]
    float* KT = QT + 64 * 132;         // [64][68]  : KT[d][c]
    float* Vs = KT + 64 * 68;          // [64][68]  : Vs[c][d]
    float* PT = Vs + 64 * 68;          // [64][132] : PT[c][r]

    const int qt = blockIdx.x;
    const int h  = blockIdx.y;
    const int b  = blockIdx.z;
    const int q0 = qt * 128;

    const float* qb = Q + (size_t)b * SS * HH + h * HDD;
    const float* kb = K + (size_t)b * SS * HH + h * HDD;
    const float* vb = V + (size_t)b * SS * HH + h * HDD;
    const float* mb = mask + (size_t)b * SS * SS + (size_t)q0 * SS;

    const int tid = threadIdx.x;
    const int ry  = tid >> 3;   // 0..31
    const int cx  = tid & 7;    // 0..7

    // Stage Q tile transposed: QT[d][r]
    for (int idx = tid; idx < 128 * 16; idx += 256) {
        const int r  = idx >> 4;
        const int d4 = (idx & 15) << 2;
        float4 t = *(const float4*)(qb + (size_t)(q0 + r) * HH + d4);
        QT[(d4 + 0) * 132 + r] = t.x;
        QT[(d4 + 1) * 132 + r] = t.y;
        QT[(d4 + 2) * 132 + r] = t.z;
        QT[(d4 + 3) * 132 + r] = t.w;
    }

    float acc[4][8];
#pragma unroll
    for (int i = 0; i < 4; i++)
#pragma unroll
        for (int j = 0; j < 8; j++) acc[i][j] = 0.0f;
    float mrow[4] = {-INFINITY, -INFINITY, -INFINITY, -INFINITY};
    float lrow[4] = {0.0f, 0.0f, 0.0f, 0.0f};

    const float scale = 0.125f;

    for (int kt = 0; kt < SS / 64; ++kt) {
        const int k0 = kt * 64;
        __syncthreads();   // protect KT/Vs/PT from prior iteration readers

        // Stage K (transposed) and V (natural) tiles
        for (int idx = tid; idx < 64 * 16; idx += 256) {
            const int r  = idx >> 4;
            const int d4 = (idx & 15) << 2;
            float4 t = *(const float4*)(kb + (size_t)(k0 + r) * HH + d4);
            KT[(d4 + 0) * 68 + r] = t.x;
            KT[(d4 + 1) * 68 + r] = t.y;
            KT[(d4 + 2) * 68 + r] = t.z;
            KT[(d4 + 3) * 68 + r] = t.w;
            float4 u = *(const float4*)(vb + (size_t)(k0 + r) * HH + d4);
            *(float4*)&Vs[r * 68 + d4] = u;
        }
        __syncthreads();

        // Scores: s[i][j] = q[ry*4+i] . k[cx*8+j]
        float s[4][8];
#pragma unroll
        for (int i = 0; i < 4; i++)
#pragma unroll
            for (int j = 0; j < 8; j++) s[i][j] = 0.0f;

#pragma unroll 8
        for (int d = 0; d < 64; ++d) {
            float4 a  = *(const float4*)&QT[d * 132 + ry * 4];
            float4 b0 = *(const float4*)&KT[d * 68 + cx * 8];
            float4 b1 = *(const float4*)&KT[d * 68 + cx * 8 + 4];
            float av[4] = {a.x, a.y, a.z, a.w};
            float bv[8] = {b0.x, b0.y, b0.z, b0.w, b1.x, b1.y, b1.z, b1.w};
#pragma unroll
            for (int i = 0; i < 4; i++)
#pragma unroll
                for (int j = 0; j < 8; j++)
                    s[i][j] = fmaf(av[i], bv[j], s[i][j]);
        }

        // Scale + additive mask, local row max
        float mloc[4];
#pragma unroll
        for (int i = 0; i < 4; i++) {
            const float* mr = mb + (size_t)(ry * 4 + i) * SS + k0 + cx * 8;
            float4 m0 = *(const float4*)mr;
            float4 m1 = *(const float4*)(mr + 4);
            float mv[8] = {m0.x, m0.y, m0.z, m0.w, m1.x, m1.y, m1.z, m1.w};
            float mx = -INFINITY;
#pragma unroll
            for (int j = 0; j < 8; j++) {
                s[i][j] = fmaf(s[i][j], scale, mv[j]);
                mx = fmaxf(mx, s[i][j]);
            }
            mloc[i] = mx;
        }
        // Row max across the 8 cx threads (lanes differ in bits 0..2)
#pragma unroll
        for (int off = 1; off < 8; off <<= 1)
#pragma unroll
            for (int i = 0; i < 4; i++)
                mloc[i] = fmaxf(mloc[i], __shfl_xor_sync(0xffffffffu, mloc[i], off));

        float alpha[4], lsum[4];
#pragma unroll
        for (int i = 0; i < 4; i++) {
            const float mnew = fmaxf(mrow[i], mloc[i]);
            alpha[i] = __expf(mrow[i] - mnew);
            mrow[i]  = mnew;
            float ls = 0.0f;
#pragma unroll
            for (int j = 0; j < 8; j++) {
                s[i][j] = __expf(s[i][j] - mnew);
                ls += s[i][j];
            }
            lsum[i] = ls;
        }
#pragma unroll
        for (int off = 1; off < 8; off <<= 1)
#pragma unroll
            for (int i = 0; i < 4; i++)
                lsum[i] += __shfl_xor_sync(0xffffffffu, lsum[i], off);
#pragma unroll
        for (int i = 0; i < 4; i++) {
            lrow[i] = lrow[i] * alpha[i] + lsum[i];
#pragma unroll
            for (int j = 0; j < 8; j++) acc[i][j] *= alpha[i];
        }

        // Write P transposed: PT[c][r]
#pragma unroll
        for (int j = 0; j < 8; j++) {
            float4 pv4 = make_float4(s[0][j], s[1][j], s[2][j], s[3][j]);
            *(float4*)&PT[(cx * 8 + j) * 132 + ry * 4] = pv4;
        }
        __syncthreads();

        // acc += P @ V : acc[i][j] += P[r][kk] * V[kk][dim]
#pragma unroll 8
        for (int kk = 0; kk < 64; ++kk) {
            float4 a  = *(const float4*)&PT[kk * 132 + ry * 4];
            float4 b0 = *(const float4*)&Vs[kk * 68 + cx * 8];
            float4 b1 = *(const float4*)&Vs[kk * 68 + cx * 8 + 4];
            float av[4] = {a.x, a.y, a.z, a.w};
            float bv[8] = {b0.x, b0.y, b0.z, b0.w, b1.x, b1.y, b1.z, b1.w};
#pragma unroll
            for (int i = 0; i < 4; i++)
#pragma unroll
                for (int j = 0; j < 8; j++)
                    acc[i][j] = fmaf(av[i], bv[j], acc[i][j]);
        }
    }

    // Epilogue: ctx[b, q0+r, h*64 + d] = acc / l
#pragma unroll
    for (int i = 0; i < 4; i++) {
        const float inv = 1.0f / lrow[i];
        const int row = q0 + ry * 4 + i;
        float* op = ctx + (size_t)(b * SS + row) * HH + h * HDD + cx * 8;
        *(float4*)(op)     = make_float4(acc[i][0] * inv, acc[i][1] * inv,
                                         acc[i][2] * inv, acc[i][3] * inv);
        *(float4*)(op + 4) = make_float4(acc[i][4] * inv, acc[i][5] * inv,
                                         acc[i][6] * inv, acc[i][7] * inv);
    }
}

// ----------------------------------------------------------------------------
// Launch
// ----------------------------------------------------------------------------
extern "C" void kernel_launch(void* const* d_in, const int* in_sizes, int n_in,
                              void* d_out, int out_size)
{
    const float* hs  = (const float*)d_in[0];
    const float* msk = (const float*)d_in[1];
    const float* q_s = (const float*)d_in[2];
    const float* q_d = (const float*)d_in[3];
    const float* k_s = (const float*)d_in[4];
    const float* k_d = (const float*)d_in[5];
    const float* v_s = (const float*)d_in[6];
    const float* v_d = (const float*)d_in[7];
    const float* o_s = (const float*)d_in[8];
    const float* o_d = (const float*)d_in[9];
    float* out = (float*)d_out;

    void *pq_, *pk_, *pv_, *pc_;
    cudaGetSymbolAddress(&pq_, g_q);
    cudaGetSymbolAddress(&pk_, g_k);
    cudaGetSymbolAddress(&pv_, g_v);
    cudaGetSymbolAddress(&pc_, g_ctx);
    float* pq = (float*)pq_;
    float* pk = (float*)pk_;
    float* pv = (float*)pv_;
    float* pc = (float*)pc_;

    const int M = BB * SS;   // 4096
    const int N = HH;        // 1024
    const int K = HH;        // 1024

    dim3 ggrid(N / 128, M / 128);   // (8, 32)

    gemm_dual<<<ggrid, 256>>>(hs, q_s, q_d, pq, M, N, K);
    gemm_dual<<<ggrid, 256>>>(hs, k_s, k_d, pk, M, N, K);
    gemm_dual<<<ggrid, 256>>>(hs, v_s, v_d, pv, M, N, K);

    const int attn_smem = (64 * 132 + 64 * 68 + 64 * 68 + 64 * 132) * 4; // 102400
    cudaFuncSetAttribute(attn_kernel, cudaFuncAttributeMaxDynamicSharedMemorySize,
                         attn_smem);
    dim3 agrid(SS / 128, NHH, BB);  // (16, 16, 2)
    attn_kernel<<<agrid, 256, attn_smem>>>(pq, pk, pv, msk, pc);

    gemm_dual<<<ggrid, 256>>>(pc, o_s, o_d, out, M, N, K);
}

// round 3
// speedup vs baseline: 1.9896x; 1.9896x over previous
#include <cuda_runtime.h>
#include <cuda_bf16.h>
#include <math.h>
#include <stdint.h>

// Problem constants
#define BB   2
#define SS   2048
#define HH   1024
#define NHH  16
#define HDD  64
#define MM   (BB * SS)          // 4096 rows

// ---------------------------------------------------------------------------
// Scratch (device globals: allocation-free contract)
// ---------------------------------------------------------------------------
__device__ __align__(256) float g_q[MM * HH];
__device__ __align__(256) float g_k[MM * HH];
__device__ __align__(256) float g_v[MM * HH];
__device__ __align__(256) float g_ctx[MM * HH];

// bf16 limb-split scratch: activations (hs limbs 0..2, ctx limbs 0..2)
__device__ __align__(256) __nv_bfloat16 g_act[6][MM * HH];
// weights: q(0..2), k(3..5), v(6..8), o(9..11)
__device__ __align__(256) __nv_bfloat16 g_wsp[12][HH * HH];

// ---------------------------------------------------------------------------
// Limb split: out limbs l0+l1+l2 ~= A (+ B), each bf16, exact residual chain.
// ---------------------------------------------------------------------------
__global__ void __launch_bounds__(256) split_dual3(
    const float4* __restrict__ A, const float4* __restrict__ B,
    __nv_bfloat16* __restrict__ L0, __nv_bfloat16* __restrict__ L1,
    __nv_bfloat16* __restrict__ L2, int n4)
{
    int i = blockIdx.x * 256 + threadIdx.x;
    if (i >= n4) return;
    float4 a = A[i];
    if (B) {
        float4 b = B[i];
        a.x += b.x; a.y += b.y; a.z += b.z; a.w += b.w;
    }
    float v[4] = {a.x, a.y, a.z, a.w};
    __align__(8) __nv_bfloat16 o0[4], o1[4], o2[4];
#pragma unroll
    for (int t = 0; t < 4; ++t) {
        float x = v[t];
        __nv_bfloat16 c0 = __float2bfloat16(x);
        float r = x - __bfloat162float(c0);
        __nv_bfloat16 c1 = __float2bfloat16(r);
        r -= __bfloat162float(c1);
        __nv_bfloat16 c2 = __float2bfloat16(r);
        o0[t] = c0; o1[t] = c1; o2[t] = c2;
    }
    *(uint2*)(L0 + 4 * (size_t)i) = *(uint2*)o0;
    *(uint2*)(L1 + 4 * (size_t)i) = *(uint2*)o1;
    *(uint2*)(L2 + 4 * (size_t)i) = *(uint2*)o2;
}

// ---------------------------------------------------------------------------
// mma.sync helpers
// ---------------------------------------------------------------------------
__device__ __forceinline__ void ldsm4(uint32_t* r, uint32_t addr) {
    asm volatile("ldmatrix.sync.aligned.m8n8.x4.shared.b16 {%0,%1,%2,%3}, [%4];"
                 : "=r"(r[0]), "=r"(r[1]), "=r"(r[2]), "=r"(r[3]) : "r"(addr));
}

__device__ __forceinline__ void hmma(float* c, const uint32_t* a, const uint32_t* b) {
    asm volatile(
        "mma.sync.aligned.m16n8k16.row.col.f32.bf16.bf16.f32 "
        "{%0,%1,%2,%3}, {%4,%5,%6,%7}, {%8,%9}, {%0,%1,%2,%3};"
        : "+f"(c[0]), "+f"(c[1]), "+f"(c[2]), "+f"(c[3])
        : "r"(a[0]), "r"(a[1]), "r"(a[2]), "r"(a[3]), "r"(b[0]), "r"(b[1]));
}

// ---------------------------------------------------------------------------
// HMMA bf16 multi-limb GEMM: C[M,1024] = A[M,1024] @ W[1024,1024]^T
// (both operands K-major). NL limbs per operand; products with i+j < NL
// accumulate into fp32 registers.
// 128x128 block tile, 8 warps (2x4), warp tile 64x32, K-stage 32,
// double-buffered cp.async. Rows padded to 40 bf16 (80B) -> conflict-free.
// ---------------------------------------------------------------------------
template <int NL>
__global__ void __launch_bounds__(256) mma_gemm(
    const __nv_bfloat16* __restrict__ a0, const __nv_bfloat16* __restrict__ a1,
    const __nv_bfloat16* __restrict__ a2,
    const __nv_bfloat16* __restrict__ b0, const __nv_bfloat16* __restrict__ b1,
    const __nv_bfloat16* __restrict__ b2,
    float* __restrict__ C)
{
    constexpr int NT     = 2 * NL;         // limb tiles per stage
    constexpr int TILEB  = 128 * 80;       // [128 rows][40 bf16] = 10240 B
    constexpr int STAGEB = NT * TILEB;

    extern __shared__ __align__(128) char smem[];
    const uint32_t sb = (uint32_t)__cvta_generic_to_shared(smem);

    const int tid  = threadIdx.x;
    const int lane = tid & 31;
    const int wid  = tid >> 5;
    const int wm   = wid >> 2;     // 0..1
    const int wn   = wid & 3;      // 0..3
    const int m0   = blockIdx.y * 128;
    const int n0   = blockIdx.x * 128;

    const __nv_bfloat16* srcs[NT];
    srcs[0] = a0 + (size_t)m0 * 1024;
    srcs[1] = a1 + (size_t)m0 * 1024;
    if constexpr (NL == 3) {
        srcs[2] = a2 + (size_t)m0 * 1024;
        srcs[3] = b0 + (size_t)n0 * 1024;
        srcs[4] = b1 + (size_t)n0 * 1024;
        srcs[5] = b2 + (size_t)n0 * 1024;
    } else {
        srcs[2] = b0 + (size_t)n0 * 1024;
        srcs[3] = b1 + (size_t)n0 * 1024;
    }

    auto load_stage = [&](int s) {
        const int k0 = s * 32;
        const uint32_t dstb = sb + (s & 1) * STAGEB;
#pragma unroll
        for (int t = 0; t < NT; ++t) {
#pragma unroll
            for (int i = 0; i < 2; ++i) {
                const int idx = tid + 256 * i;        // 0..511
                const int row = idx >> 2;
                const int ch  = idx & 3;
                uint32_t dst = dstb + t * TILEB + row * 80 + ch * 16;
                const void* src = srcs[t] + (size_t)row * 1024 + k0 + ch * 8;
                asm volatile("cp.async.cg.shared.global [%0], [%1], 16;"
                             :: "r"(dst), "l"(src) : "memory");
            }
        }
        asm volatile("cp.async.commit_group;" ::: "memory");
    };

    // Per-thread ldmatrix base offsets (within a limb tile)
    const uint32_t aoff = (uint32_t)((wm * 64 + (lane & 15)) * 80 + ((lane >> 4) & 1) * 16);
    const uint32_t boff = (uint32_t)((wn * 32 + ((lane >> 4) & 1) * 8 + (lane & 7)) * 80
                                     + ((lane >> 3) & 1) * 16);

    float acc[4][4][4];
#pragma unroll
    for (int mf = 0; mf < 4; ++mf)
#pragma unroll
        for (int nf = 0; nf < 4; ++nf)
#pragma unroll
            for (int r = 0; r < 4; ++r) acc[mf][nf][r] = 0.0f;

    load_stage(0);
    load_stage(1);

    for (int s = 0; s < 32; ++s) {
        if (s == 31) asm volatile("cp.async.wait_group 0;" ::: "memory");
        else         asm volatile("cp.async.wait_group 1;" ::: "memory");
        __syncthreads();

        const uint32_t st = sb + (s & 1) * STAGEB;
#pragma unroll
        for (int kh = 0; kh < 2; ++kh) {          // kk = kh*16
            const uint32_t kB = (uint32_t)(kh * 32);   // 16 bf16 = 32 bytes
            uint32_t Af[NL][4][4];
            uint32_t Bf[NL][2][4];
#pragma unroll
            for (int l = 0; l < NL; ++l) {
#pragma unroll
                for (int mf = 0; mf < 4; ++mf)
                    ldsm4(Af[l][mf], st + l * TILEB + aoff + mf * 16 * 80 + kB);
#pragma unroll
                for (int pr = 0; pr < 2; ++pr)
                    ldsm4(Bf[l][pr], st + (NL + l) * TILEB + boff + pr * 16 * 80 + kB);
            }
#pragma unroll
            for (int i = 0; i < NL; ++i)
#pragma unroll
                for (int j = 0; j < NL; ++j) {
                    if (i + j >= NL) continue;
#pragma unroll
                    for (int mf = 0; mf < 4; ++mf)
#pragma unroll
                        for (int pr = 0; pr < 2; ++pr) {
                            hmma(acc[mf][pr * 2 + 0], Af[i][mf], &Bf[j][pr][0]);
                            hmma(acc[mf][pr * 2 + 1], Af[i][mf], &Bf[j][pr][2]);
                        }
                }
        }
        __syncthreads();
        if (s + 2 < 32) load_stage(s + 2);
    }

    // Epilogue: write fp32
    const int mrow = m0 + wm * 64 + (lane >> 2);
    const int ncol = n0 + wn * 32 + (lane & 3) * 2;
#pragma unroll
    for (int mf = 0; mf < 4; ++mf)
#pragma unroll
        for (int nf = 0; nf < 4; ++nf) {
            float* p0 = C + (size_t)(mrow + mf * 16) * 1024 + ncol + nf * 8;
            float* p1 = C + (size_t)(mrow + mf * 16 + 8) * 1024 + ncol + nf * 8;
            *(float2*)p0 = make_float2(acc[mf][nf][0], acc[mf][nf][1]);
            *(float2*)p1 = make_float2(acc[mf][nf][2], acc[mf][nf][3]);
        }
}

// ---------------------------------------------------------------------------
// Flash attention, fp32, online softmax (unchanged — converts next round)
// ---------------------------------------------------------------------------
__global__ void __launch_bounds__(256) attn_kernel(
    const float* __restrict__ Q,
    const float* __restrict__ K,
    const float* __restrict__ V,
    const float* __restrict__ mask,
    float* __restrict__ ctx)
{
    extern __shared__ float sm[];
    float* QT = sm;                    // [64][132]
    float* KT = QT + 64 * 132;         // [64][68]
    float* Vs = KT + 64 * 68;          // [64][68]
    float* PT = Vs + 64 * 68;          // [64][132]

    const int qt = blockIdx.x;
    const int h  = blockIdx.y;
    const int b  = blockIdx.z;
    const int q0 = qt * 128;

    const float* qb = Q + (size_t)b * SS * HH + h * HDD;
    const float* kb = K + (size_t)b * SS * HH + h * HDD;
    const float* vb = V + (size_t)b * SS * HH + h * HDD;
    const float* mb = mask + (size_t)b * SS * SS + (size_t)q0 * SS;

    const int tid = threadIdx.x;
    const int ry  = tid >> 3;
    const int cx  = tid & 7;

    for (int idx = tid; idx < 128 * 16; idx += 256) {
        const int r  = idx >> 4;
        const int d4 = (idx & 15) << 2;
        float4 t = *(const float4*)(qb + (size_t)(q0 + r) * HH + d4);
        QT[(d4 + 0) * 132 + r] = t.x;
        QT[(d4 + 1) * 132 + r] = t.y;
        QT[(d4 + 2) * 132 + r] = t.z;
        QT[(d4 + 3) * 132 + r] = t.w;
    }

    float acc[4][8];
#pragma unroll
    for (int i = 0; i < 4; i++)
#pragma unroll
        for (int j = 0; j < 8; j++) acc[i][j] = 0.0f;
    float mrow[4] = {-INFINITY, -INFINITY, -INFINITY, -INFINITY};
    float lrow[4] = {0.0f, 0.0f, 0.0f, 0.0f};

    const float scale = 0.125f;

    for (int kt = 0; kt < SS / 64; ++kt) {
        const int k0 = kt * 64;
        __syncthreads();

        for (int idx = tid; idx < 64 * 16; idx += 256) {
            const int r  = idx >> 4;
            const int d4 = (idx & 15) << 2;
            float4 t = *(const float4*)(kb + (size_t)(k0 + r) * HH + d4);
            KT[(d4 + 0) * 68 + r] = t.x;
            KT[(d4 + 1) * 68 + r] = t.y;
            KT[(d4 + 2) * 68 + r] = t.z;
            KT[(d4 + 3) * 68 + r] = t.w;
            float4 u = *(const float4*)(vb + (size_t)(k0 + r) * HH + d4);
            *(float4*)&Vs[r * 68 + d4] = u;
        }
        __syncthreads();

        float s[4][8];
#pragma unroll
        for (int i = 0; i < 4; i++)
#pragma unroll
            for (int j = 0; j < 8; j++) s[i][j] = 0.0f;

#pragma unroll 8
        for (int d = 0; d < 64; ++d) {
            float4 a  = *(const float4*)&QT[d * 132 + ry * 4];
            float4 v0 = *(const float4*)&KT[d * 68 + cx * 8];
            float4 v1 = *(const float4*)&KT[d * 68 + cx * 8 + 4];
            float av[4] = {a.x, a.y, a.z, a.w};
            float bv[8] = {v0.x, v0.y, v0.z, v0.w, v1.x, v1.y, v1.z, v1.w};
#pragma unroll
            for (int i = 0; i < 4; i++)
#pragma unroll
                for (int j = 0; j < 8; j++)
                    s[i][j] = fmaf(av[i], bv[j], s[i][j]);
        }

        float mloc[4];
#pragma unroll
        for (int i = 0; i < 4; i++) {
            const float* mr = mb + (size_t)(ry * 4 + i) * SS + k0 + cx * 8;
            float4 m0 = *(const float4*)mr;
            float4 m1 = *(const float4*)(mr + 4);
            float mv[8] = {m0.x, m0.y, m0.z, m0.w, m1.x, m1.y, m1.z, m1.w};
            float mx = -INFINITY;
#pragma unroll
            for (int j = 0; j < 8; j++) {
                s[i][j] = fmaf(s[i][j], scale, mv[j]);
                mx = fmaxf(mx, s[i][j]);
            }
            mloc[i] = mx;
        }
#pragma unroll
        for (int off = 1; off < 8; off <<= 1)
#pragma unroll
            for (int i = 0; i < 4; i++)
                mloc[i] = fmaxf(mloc[i], __shfl_xor_sync(0xffffffffu, mloc[i], off));

        float alpha[4], lsum[4];
#pragma unroll
        for (int i = 0; i < 4; i++) {
            const float mnew = fmaxf(mrow[i], mloc[i]);
            alpha[i] = __expf(mrow[i] - mnew);
            mrow[i]  = mnew;
            float ls = 0.0f;
#pragma unroll
            for (int j = 0; j < 8; j++) {
                s[i][j] = __expf(s[i][j] - mnew);
                ls += s[i][j];
            }
            lsum[i] = ls;
        }
#pragma unroll
        for (int off = 1; off < 8; off <<= 1)
#pragma unroll
            for (int i = 0; i < 4; i++)
                lsum[i] += __shfl_xor_sync(0xffffffffu, lsum[i], off);
#pragma unroll
        for (int i = 0; i < 4; i++) {
            lrow[i] = lrow[i] * alpha[i] + lsum[i];
#pragma unroll
            for (int j = 0; j < 8; j++) acc[i][j] *= alpha[i];
        }

#pragma unroll
        for (int j = 0; j < 8; j++) {
            float4 pv4 = make_float4(s[0][j], s[1][j], s[2][j], s[3][j]);
            *(float4*)&PT[(cx * 8 + j) * 132 + ry * 4] = pv4;
        }
        __syncthreads();

#pragma unroll 8
        for (int kk = 0; kk < 64; ++kk) {
            float4 a  = *(const float4*)&PT[kk * 132 + ry * 4];
            float4 v0 = *(const float4*)&Vs[kk * 68 + cx * 8];
            float4 v1 = *(const float4*)&Vs[kk * 68 + cx * 8 + 4];
            float av[4] = {a.x, a.y, a.z, a.w};
            float bv[8] = {v0.x, v0.y, v0.z, v0.w, v1.x, v1.y, v1.z, v1.w};
#pragma unroll
            for (int i = 0; i < 4; i++)
#pragma unroll
                for (int j = 0; j < 8; j++)
                    acc[i][j] = fmaf(av[i], bv[j], acc[i][j]);
        }
    }

#pragma unroll
    for (int i = 0; i < 4; i++) {
        const float inv = 1.0f / lrow[i];
        const int row = q0 + ry * 4 + i;
        float* op = ctx + (size_t)(b * SS + row) * HH + h * HDD + cx * 8;
        *(float4*)(op)     = make_float4(acc[i][0] * inv, acc[i][1] * inv,
                                         acc[i][2] * inv, acc[i][3] * inv);
        *(float4*)(op + 4) = make_float4(acc[i][4] * inv, acc[i][5] * inv,
                                         acc[i][6] * inv, acc[i][7] * inv);
    }
}

// ---------------------------------------------------------------------------
// Launch
// ---------------------------------------------------------------------------
extern "C" void kernel_launch(void* const* d_in, const int* in_sizes, int n_in,
                              void* d_out, int out_size)
{
    const float* hs  = (const float*)d_in[0];
    const float* msk = (const float*)d_in[1];
    const float* q_s = (const float*)d_in[2];
    const float* q_d = (const float*)d_in[3];
    const float* k_s = (const float*)d_in[4];
    const float* k_d = (const float*)d_in[5];
    const float* v_s = (const float*)d_in[6];
    const float* v_d = (const float*)d_in[7];
    const float* o_s = (const float*)d_in[8];
    const float* o_d = (const float*)d_in[9];
    float* out = (float*)d_out;

    void* p;
    cudaGetSymbolAddress(&p, g_q);   float* pq = (float*)p;
    cudaGetSymbolAddress(&p, g_k);   float* pk = (float*)p;
    cudaGetSymbolAddress(&p, g_v);   float* pv = (float*)p;
    cudaGetSymbolAddress(&p, g_ctx); float* pc = (float*)p;
    cudaGetSymbolAddress(&p, g_act); __nv_bfloat16* act = (__nv_bfloat16*)p;
    cudaGetSymbolAddress(&p, g_wsp); __nv_bfloat16* wsp = (__nv_bfloat16*)p;

    const size_t AE = (size_t)MM * HH;
    const size_t WE = (size_t)HH * HH;
    __nv_bfloat16* hs0 = act;            __nv_bfloat16* hs1 = act + AE;
    __nv_bfloat16* hs2 = act + 2 * AE;
    __nv_bfloat16* cx0 = act + 3 * AE;   __nv_bfloat16* cx1 = act + 4 * AE;
    __nv_bfloat16* cx2 = act + 5 * AE;
    __nv_bfloat16* wq0 = wsp;            __nv_bfloat16* wq1 = wsp + WE;
    __nv_bfloat16* wq2 = wsp + 2 * WE;
    __nv_bfloat16* wk0 = wsp + 3 * WE;   __nv_bfloat16* wk1 = wsp + 4 * WE;
    __nv_bfloat16* wk2 = wsp + 5 * WE;
    __nv_bfloat16* wv0 = wsp + 6 * WE;   __nv_bfloat16* wv1 = wsp + 7 * WE;
    __nv_bfloat16* wv2 = wsp + 8 * WE;
    __nv_bfloat16* wo0 = wsp + 9 * WE;   __nv_bfloat16* wo1 = wsp + 10 * WE;
    __nv_bfloat16* wo2 = wsp + 11 * WE;

    // Limb splits
    split_dual3<<<(int)(AE / 4 / 256), 256>>>((const float4*)hs, nullptr,
                                              hs0, hs1, hs2, (int)(AE / 4));
    split_dual3<<<(int)(WE / 4 / 256), 256>>>((const float4*)q_s, (const float4*)q_d,
                                              wq0, wq1, wq2, (int)(WE / 4));
    split_dual3<<<(int)(WE / 4 / 256), 256>>>((const float4*)k_s, (const float4*)k_d,
                                              wk0, wk1, wk2, (int)(WE / 4));
    split_dual3<<<(int)(WE / 4 / 256), 256>>>((const float4*)v_s, (const float4*)v_d,
                                              wv0, wv1, wv2, (int)(WE / 4));
    split_dual3<<<(int)(WE / 4 / 256), 256>>>((const float4*)o_s, (const float4*)o_d,
                                              wo0, wo1, wo2, (int)(WE / 4));

    // HMMA GEMMs
    const int SMEM3 = 2 * 6 * 10240;   // 122880
    const int SMEM2 = 2 * 4 * 10240;   // 81920
    cudaFuncSetAttribute(mma_gemm<3>, cudaFuncAttributeMaxDynamicSharedMemorySize, SMEM3);
    cudaFuncSetAttribute(mma_gemm<2>, cudaFuncAttributeMaxDynamicSharedMemorySize, SMEM2);
    dim3 gg(HH / 128, MM / 128);   // (8, 32)

    mma_gemm<3><<<gg, 256, SMEM3>>>(hs0, hs1, hs2, wq0, wq1, wq2, pq);
    mma_gemm<3><<<gg, 256, SMEM3>>>(hs0, hs1, hs2, wk0, wk1, wk2, pk);
    mma_gemm<2><<<gg, 256, SMEM2>>>(hs0, hs1, nullptr, wv0, wv1, nullptr, pv);

    // Attention (fp32, unchanged)
    const int attn_smem = (64 * 132 + 64 * 68 + 64 * 68 + 64 * 132) * 4;
    cudaFuncSetAttribute(attn_kernel, cudaFuncAttributeMaxDynamicSharedMemorySize,
                         attn_smem);
    dim3 agrid(SS / 128, NHH, BB);
    attn_kernel<<<agrid, 256, attn_smem>>>(pq, pk, pv, msk, pc);

    // O projection
    split_dual3<<<(int)(AE / 4 / 256), 256>>>((const float4*)pc, nullptr,
                                              cx0, cx1, cx2, (int)(AE / 4));
    mma_gemm<2><<<gg, 256, SMEM2>>>(cx0, cx1, nullptr, wo0, wo1, nullptr, out);
}

// round 4
// speedup vs baseline: 4.2625x; 2.1424x over previous
#include <cuda_runtime.h>
#include <cuda_bf16.h>
#include <math.h>
#include <stdint.h>

// Problem constants
#define BB   2
#define SS   2048
#define HH   1024
#define NHH  16
#define HDD  64
#define MM   (BB * SS)          // 4096 rows

typedef __nv_bfloat16 bf16;

// ---------------------------------------------------------------------------
// Scratch (device globals: allocation-free contract)
// ---------------------------------------------------------------------------
// hs limbs (3)
__device__ __align__(256) bf16 g_hs[3][MM * HH];
// weight limbs: q(0..2), k(3..5), v(6..8), o(9..11)
__device__ __align__(256) bf16 g_wsp[12][HH * HH];
// Q,K,V,ctx as 2-limb bf16
__device__ __align__(256) bf16 g_qkv[6][MM * HH];   // q0,q1,k0,k1,v0,v1
__device__ __align__(256) bf16 g_cx[2][MM * HH];    // ctx limbs

// ---------------------------------------------------------------------------
// Limb split: l0+l1+l2 ~= A (+ B), each bf16, residual chain.
// ---------------------------------------------------------------------------
__global__ void __launch_bounds__(256) split_dual3(
    const float4* __restrict__ A, const float4* __restrict__ B,
    bf16* __restrict__ L0, bf16* __restrict__ L1, bf16* __restrict__ L2, int n4)
{
    int i = blockIdx.x * 256 + threadIdx.x;
    if (i >= n4) return;
    float4 a = A[i];
    if (B) {
        float4 b = B[i];
        a.x += b.x; a.y += b.y; a.z += b.z; a.w += b.w;
    }
    float v[4] = {a.x, a.y, a.z, a.w};
    __align__(8) bf16 o0[4], o1[4], o2[4];
#pragma unroll
    for (int t = 0; t < 4; ++t) {
        float x = v[t];
        bf16 c0 = __float2bfloat16(x);
        float r = x - __bfloat162float(c0);
        bf16 c1 = __float2bfloat16(r);
        r -= __bfloat162float(c1);
        bf16 c2 = __float2bfloat16(r);
        o0[t] = c0; o1[t] = c1; o2[t] = c2;
    }
    *(uint2*)(L0 + 4 * (size_t)i) = *(uint2*)o0;
    *(uint2*)(L1 + 4 * (size_t)i) = *(uint2*)o1;
    *(uint2*)(L2 + 4 * (size_t)i) = *(uint2*)o2;
}

// ---------------------------------------------------------------------------
// mma.sync helpers
// ---------------------------------------------------------------------------
__device__ __forceinline__ void ldsm4(uint32_t* r, uint32_t addr) {
    asm volatile("ldmatrix.sync.aligned.m8n8.x4.shared.b16 {%0,%1,%2,%3}, [%4];"
                 : "=r"(r[0]), "=r"(r[1]), "=r"(r[2]), "=r"(r[3]) : "r"(addr));
}
__device__ __forceinline__ void ldsm4t(uint32_t* r, uint32_t addr) {
    asm volatile("ldmatrix.sync.aligned.m8n8.x4.trans.shared.b16 {%0,%1,%2,%3}, [%4];"
                 : "=r"(r[0]), "=r"(r[1]), "=r"(r[2]), "=r"(r[3]) : "r"(addr));
}
__device__ __forceinline__ void hmma(float* c, const uint32_t* a,
                                     uint32_t b0, uint32_t b1) {
    asm volatile(
        "mma.sync.aligned.m16n8k16.row.col.f32.bf16.bf16.f32 "
        "{%0,%1,%2,%3}, {%4,%5,%6,%7}, {%8,%9}, {%0,%1,%2,%3};"
        : "+f"(c[0]), "+f"(c[1]), "+f"(c[2]), "+f"(c[3])
        : "r"(a[0]), "r"(a[1]), "r"(a[2]), "r"(a[3]), "r"(b0), "r"(b1));
}

// ---------------------------------------------------------------------------
// HMMA multi-limb GEMM: C = A[M,1024] @ W[1024,1024]^T. NL input limbs
// (products i+j<NL). Output either fp32 C or 2-limb bf16 (L0,L1).
// 128x128 block tile, 8 warps (2x4), warp 64x32, K-stage 32, double-buffered.
// ---------------------------------------------------------------------------
template <int NL, bool LIMB>
__global__ void __launch_bounds__(256) mma_gemm(
    const bf16* __restrict__ a0, const bf16* __restrict__ a1,
    const bf16* __restrict__ a2,
    const bf16* __restrict__ b0, const bf16* __restrict__ b1,
    const bf16* __restrict__ b2,
    float* __restrict__ C, bf16* __restrict__ L0, bf16* __restrict__ L1)
{
    constexpr int NT     = 2 * NL;
    constexpr int TILEB  = 128 * 80;
    constexpr int STAGEB = NT * TILEB;

    extern __shared__ __align__(128) char smem[];
    const uint32_t sb = (uint32_t)__cvta_generic_to_shared(smem);

    const int tid  = threadIdx.x;
    const int lane = tid & 31;
    const int wid  = tid >> 5;
    const int wm   = wid >> 2;
    const int wn   = wid & 3;
    const int m0   = blockIdx.y * 128;
    const int n0   = blockIdx.x * 128;

    const bf16* srcs[NT];
    srcs[0] = a0 + (size_t)m0 * 1024;
    srcs[1] = a1 + (size_t)m0 * 1024;
    if constexpr (NL == 3) {
        srcs[2] = a2 + (size_t)m0 * 1024;
        srcs[3] = b0 + (size_t)n0 * 1024;
        srcs[4] = b1 + (size_t)n0 * 1024;
        srcs[5] = b2 + (size_t)n0 * 1024;
    } else {
        srcs[2] = b0 + (size_t)n0 * 1024;
        srcs[3] = b1 + (size_t)n0 * 1024;
    }

    auto load_stage = [&](int s) {
        const int k0 = s * 32;
        const uint32_t dstb = sb + (s & 1) * STAGEB;
#pragma unroll
        for (int t = 0; t < NT; ++t) {
#pragma unroll
            for (int i = 0; i < 2; ++i) {
                const int idx = tid + 256 * i;
                const int row = idx >> 2;
                const int ch  = idx & 3;
                uint32_t dst = dstb + t * TILEB + row * 80 + ch * 16;
                const void* src = srcs[t] + (size_t)row * 1024 + k0 + ch * 8;
                asm volatile("cp.async.cg.shared.global [%0], [%1], 16;"
                             :: "r"(dst), "l"(src) : "memory");
            }
        }
        asm volatile("cp.async.commit_group;" ::: "memory");
    };

    const uint32_t aoff = (uint32_t)((wm * 64 + (lane & 15)) * 80 + ((lane >> 4) & 1) * 16);
    const uint32_t boff = (uint32_t)((wn * 32 + ((lane >> 4) & 1) * 8 + (lane & 7)) * 80
                                     + ((lane >> 3) & 1) * 16);

    float acc[4][4][4];
#pragma unroll
    for (int mf = 0; mf < 4; ++mf)
#pragma unroll
        for (int nf = 0; nf < 4; ++nf)
#pragma unroll
            for (int r = 0; r < 4; ++r) acc[mf][nf][r] = 0.0f;

    load_stage(0);
    load_stage(1);

    for (int s = 0; s < 32; ++s) {
        if (s == 31) asm volatile("cp.async.wait_group 0;" ::: "memory");
        else         asm volatile("cp.async.wait_group 1;" ::: "memory");
        __syncthreads();

        const uint32_t st = sb + (s & 1) * STAGEB;
#pragma unroll
        for (int kh = 0; kh < 2; ++kh) {
            const uint32_t kB = (uint32_t)(kh * 32);
            uint32_t Af[NL][4][4];
            uint32_t Bf[NL][2][4];
#pragma unroll
            for (int l = 0; l < NL; ++l) {
#pragma unroll
                for (int mf = 0; mf < 4; ++mf)
                    ldsm4(Af[l][mf], st + l * TILEB + aoff + mf * 16 * 80 + kB);
#pragma unroll
                for (int pr = 0; pr < 2; ++pr)
                    ldsm4(Bf[l][pr], st + (NL + l) * TILEB + boff + pr * 16 * 80 + kB);
            }
#pragma unroll
            for (int i = 0; i < NL; ++i)
#pragma unroll
                for (int j = 0; j < NL; ++j) {
                    if (i + j >= NL) continue;
#pragma unroll
                    for (int mf = 0; mf < 4; ++mf)
#pragma unroll
                        for (int pr = 0; pr < 2; ++pr) {
                            hmma(acc[mf][pr * 2 + 0], Af[i][mf], Bf[j][pr][0], Bf[j][pr][1]);
                            hmma(acc[mf][pr * 2 + 1], Af[i][mf], Bf[j][pr][2], Bf[j][pr][3]);
                        }
                }
        }
        __syncthreads();
        if (s + 2 < 32) load_stage(s + 2);
    }

    const int mrow = m0 + wm * 64 + (lane >> 2);
    const int ncol = n0 + wn * 32 + (lane & 3) * 2;
#pragma unroll
    for (int mf = 0; mf < 4; ++mf)
#pragma unroll
        for (int nf = 0; nf < 4; ++nf) {
            const size_t r0 = (size_t)(mrow + mf * 16) * 1024 + ncol + nf * 8;
            const size_t r1 = r0 + 8 * 1024;
            if constexpr (LIMB) {
                float v0 = acc[mf][nf][0], v1 = acc[mf][nf][1];
                float v2 = acc[mf][nf][2], v3 = acc[mf][nf][3];
                __nv_bfloat162 h0 = __floats2bfloat162_rn(v0, v1);
                __nv_bfloat162 g0 = __floats2bfloat162_rn(
                    v0 - __bfloat162float(h0.x), v1 - __bfloat162float(h0.y));
                __nv_bfloat162 h1 = __floats2bfloat162_rn(v2, v3);
                __nv_bfloat162 g1 = __floats2bfloat162_rn(
                    v2 - __bfloat162float(h1.x), v3 - __bfloat162float(h1.y));
                *(uint32_t*)(L0 + r0) = *(uint32_t*)&h0;
                *(uint32_t*)(L1 + r0) = *(uint32_t*)&g0;
                *(uint32_t*)(L0 + r1) = *(uint32_t*)&h1;
                *(uint32_t*)(L1 + r1) = *(uint32_t*)&g1;
            } else {
                *(float2*)(C + r0) = make_float2(acc[mf][nf][0], acc[mf][nf][1]);
                *(float2*)(C + r1) = make_float2(acc[mf][nf][2], acc[mf][nf][3]);
            }
        }
}

// ---------------------------------------------------------------------------
// HMMA flash attention (2-limb bf16, 3 products per GEMM stage).
// Block = (q-tile 128, h, b). 8 warps: wm=wid>>1 (32 q-rows), wn=wid&1 (64 k-cols).
// K-tile 128 per iter (16 iters). Q smem-resident; K/V double-buffered.
// Rows padded to 144B (conflict-free ldsm). P limbs built in registers
// (C-frag == A-frag identity). Output written as 2-limb bf16 ctx.
// ---------------------------------------------------------------------------
#define ATILE 18432           // 128 rows * 144B
#define ASTAGE (4 * ATILE)    // K0,K1,V0,V1

__global__ void __launch_bounds__(256, 1) attn_mma(
    const bf16* __restrict__ q0l, const bf16* __restrict__ q1l,
    const bf16* __restrict__ k0l, const bf16* __restrict__ k1l,
    const bf16* __restrict__ v0l, const bf16* __restrict__ v1l,
    const float* __restrict__ mask,
    bf16* __restrict__ cx0, bf16* __restrict__ cx1)
{
    extern __shared__ __align__(128) char smem[];
    const uint32_t sb   = (uint32_t)__cvta_generic_to_shared(smem);
    const uint32_t kvb  = sb;
    const uint32_t qbse = sb + 2 * ASTAGE;
    float* redm = (float*)(smem + 2 * ASTAGE + 2 * ATILE);        // [2][128]
    float* redl = redm + 256;                                      // [2][128]

    const int tid  = threadIdx.x;
    const int lane = tid & 31;
    const int wid  = tid >> 5;
    const int wm   = wid >> 1;          // 0..3 : 32 q-rows
    const int wn   = wid & 1;           // 0..1 : 64 k-cols
    const int qt = blockIdx.x, h = blockIdx.y, b = blockIdx.z;
    const int q0r = qt * 128;

    const size_t hb = (size_t)b * SS * HH + (size_t)h * HDD;
    const bf16* qsrc[2] = {q0l + hb + (size_t)q0r * HH, q1l + hb + (size_t)q0r * HH};
    const bf16* ksrc[2] = {k0l + hb, k1l + hb};
    const bf16* vsrc[2] = {v0l + hb, v1l + hb};
    const float* maskb = mask + (size_t)b * SS * SS;

    // ---- prologue loads ----
#pragma unroll
    for (int i = 0; i < 8; ++i) {                       // Q: 2048 chunks
        const int idx = tid + 256 * i;
        const int limb = idx >> 10;
        const int rem  = idx & 1023;
        const int r = rem >> 3, c = rem & 7;
        uint32_t dst = qbse + limb * ATILE + r * 144 + c * 16;
        const void* src = qsrc[limb] + (size_t)r * HH + c * 8;
        asm volatile("cp.async.cg.shared.global [%0], [%1], 16;"
                     :: "r"(dst), "l"(src) : "memory");
    }
    auto load_kv = [&](int s) {
        const int k00 = s * 128;
        const uint32_t dstb = kvb + (s & 1) * ASTAGE;
#pragma unroll
        for (int i = 0; i < 16; ++i) {                  // 4096 chunks
            const int idx = tid + 256 * i;
            const int t   = idx >> 10;
            const int rem = idx & 1023;
            const int r = rem >> 3, c = rem & 7;
            uint32_t dst = dstb + t * ATILE + r * 144 + c * 16;
            const bf16* base = (t < 2) ? ksrc[t] : vsrc[t - 2];
            const void* src = base + (size_t)(k00 + r) * HH + c * 8;
            asm volatile("cp.async.cg.shared.global [%0], [%1], 16;"
                         :: "r"(dst), "l"(src) : "memory");
        }
        asm volatile("cp.async.commit_group;" ::: "memory");
    };
    load_kv(0);   // group0 = Q + kv0
    load_kv(1);   // group1 = kv1

    float O[2][8][4];
#pragma unroll
    for (int mf = 0; mf < 2; ++mf)
#pragma unroll
        for (int dn = 0; dn < 8; ++dn)
#pragma unroll
            for (int r = 0; r < 4; ++r) O[mf][dn][r] = 0.0f;
    float mst[4] = {-INFINITY, -INFINITY, -INFINITY, -INFINITY};
    float lst[4] = {0.0f, 0.0f, 0.0f, 0.0f};

    const int rloc = (lane >> 2);      // 0..7 row within 8-row group
    const float scale = 0.125f;

    for (int s = 0; s < 16; ++s) {
        if (s == 15) asm volatile("cp.async.wait_group 0;" ::: "memory");
        else         asm volatile("cp.async.wait_group 1;" ::: "memory");
        __syncthreads();
        const uint32_t kvs = kvb + (s & 1) * ASTAGE;

        // ---- QK^T : S[2][8][4] ----
        float S[2][8][4];
#pragma unroll
        for (int mf = 0; mf < 2; ++mf)
#pragma unroll
            for (int nf = 0; nf < 8; ++nf)
#pragma unroll
                for (int r = 0; r < 4; ++r) S[mf][nf][r] = 0.0f;

#pragma unroll
        for (int ch = 0; ch < 4; ++ch) {
            uint32_t A[2][2][4];   // [limb][mf]
#pragma unroll
            for (int l = 0; l < 2; ++l)
#pragma unroll
                for (int mf = 0; mf < 2; ++mf)
                    ldsm4(A[l][mf], qbse + l * ATILE
                          + (wm * 32 + mf * 16 + (lane & 15)) * 144
                          + ch * 32 + ((lane >> 4) & 1) * 16);
#pragma unroll
            for (int bp = 0; bp < 4; ++bp) {
                uint32_t B0[4], B1[4];
                const uint32_t ba = kvs
                    + (wn * 64 + bp * 16 + ((lane >> 4) & 1) * 8 + (lane & 7)) * 144
                    + ((lane >> 3) & 1) * 16 + ch * 32;
                ldsm4(B0, ba);
                ldsm4(B1, ba + ATILE);
#pragma unroll
                for (int mf = 0; mf < 2; ++mf) {
                    hmma(S[mf][2 * bp + 0], A[0][mf], B0[0], B0[1]);   // q0k0
                    hmma(S[mf][2 * bp + 1], A[0][mf], B0[2], B0[3]);
                    hmma(S[mf][2 * bp + 0], A[0][mf], B1[0], B1[1]);   // q0k1
                    hmma(S[mf][2 * bp + 1], A[0][mf], B1[2], B1[3]);
                    hmma(S[mf][2 * bp + 0], A[1][mf], B0[0], B0[1]);   // q1k0
                    hmma(S[mf][2 * bp + 1], A[1][mf], B0[2], B0[3]);
                }
            }
        }

        // ---- scale + mask + local row max ----
        float mloc[4];
#pragma unroll
        for (int sl = 0; sl < 4; ++sl) mloc[sl] = -INFINITY;
#pragma unroll
        for (int mf = 0; mf < 2; ++mf)
#pragma unroll
            for (int rh = 0; rh < 2; ++rh) {
                const int row = q0r + wm * 32 + mf * 16 + rh * 8 + rloc;
                const float* mrp = maskb + (size_t)row * SS + s * 128 + wn * 64
                                   + (lane & 3) * 2;
                const int sl = mf * 2 + rh;
#pragma unroll
                for (int nf = 0; nf < 8; ++nf) {
                    float2 mv = *(const float2*)(mrp + nf * 8);
                    float a = fmaf(S[mf][nf][rh * 2 + 0], scale, mv.x);
                    float c = fmaf(S[mf][nf][rh * 2 + 1], scale, mv.y);
                    S[mf][nf][rh * 2 + 0] = a;
                    S[mf][nf][rh * 2 + 1] = c;
                    mloc[sl] = fmaxf(mloc[sl], fmaxf(a, c));
                }
            }
#pragma unroll
        for (int off = 1; off < 4; off <<= 1)
#pragma unroll
            for (int sl = 0; sl < 4; ++sl)
                mloc[sl] = fmaxf(mloc[sl], __shfl_xor_sync(0xffffffffu, mloc[sl], off));
        if ((lane & 3) == 0) {
#pragma unroll
            for (int mf = 0; mf < 2; ++mf)
#pragma unroll
                for (int rh = 0; rh < 2; ++rh)
                    redm[wn * 128 + wm * 32 + mf * 16 + rh * 8 + rloc] = mloc[mf * 2 + rh];
        }
        __syncthreads();

        float alpha[4], lsum[4];
#pragma unroll
        for (int mf = 0; mf < 2; ++mf)
#pragma unroll
            for (int rh = 0; rh < 2; ++rh) {
                const int sl = mf * 2 + rh;
                const int rr = wm * 32 + mf * 16 + rh * 8 + rloc;
                const float mw = fmaxf(redm[rr], redm[128 + rr]);
                const float mnew = fmaxf(mst[sl], mw);
                alpha[sl] = __expf(mst[sl] - mnew);
                mst[sl] = mnew;
                float ls = 0.0f;
#pragma unroll
                for (int nf = 0; nf < 8; ++nf) {
                    float a = __expf(S[mf][nf][rh * 2 + 0] - mnew);
                    float c = __expf(S[mf][nf][rh * 2 + 1] - mnew);
                    S[mf][nf][rh * 2 + 0] = a;
                    S[mf][nf][rh * 2 + 1] = c;
                    ls += a + c;
                }
                lsum[sl] = ls;
            }
#pragma unroll
        for (int off = 1; off < 4; off <<= 1)
#pragma unroll
            for (int sl = 0; sl < 4; ++sl)
                lsum[sl] += __shfl_xor_sync(0xffffffffu, lsum[sl], off);
        if ((lane & 3) == 0) {
#pragma unroll
            for (int mf = 0; mf < 2; ++mf)
#pragma unroll
                for (int rh = 0; rh < 2; ++rh)
                    redl[wn * 128 + wm * 32 + mf * 16 + rh * 8 + rloc] = lsum[mf * 2 + rh];
        }
        __syncthreads();
#pragma unroll
        for (int mf = 0; mf < 2; ++mf)
#pragma unroll
            for (int rh = 0; rh < 2; ++rh) {
                const int sl = mf * 2 + rh;
                const int rr = wm * 32 + mf * 16 + rh * 8 + rloc;
                lst[sl] = lst[sl] * alpha[sl] + redl[rr] + redl[128 + rr];
            }
        // rescale O partials
#pragma unroll
        for (int mf = 0; mf < 2; ++mf)
#pragma unroll
            for (int dn = 0; dn < 8; ++dn) {
                O[mf][dn][0] *= alpha[mf * 2 + 0];
                O[mf][dn][1] *= alpha[mf * 2 + 0];
                O[mf][dn][2] *= alpha[mf * 2 + 1];
                O[mf][dn][3] *= alpha[mf * 2 + 1];
            }

        // ---- PV : O += P @ V over this warp's 64 k-cols ----
#pragma unroll
        for (int kch = 0; kch < 4; ++kch) {
            // build P limb A-frags from S (C-frag == A-frag identity)
            uint32_t P0[2][4], P1[2][4];
#pragma unroll
            for (int mf = 0; mf < 2; ++mf) {
#pragma unroll
                for (int half = 0; half < 2; ++half) {     // nf = 2*kch + half
                    const float* c = S[mf][2 * kch + half];
                    __nv_bfloat162 t0 = __floats2bfloat162_rn(c[0], c[1]);
                    __nv_bfloat162 t1 = __floats2bfloat162_rn(c[2], c[3]);
                    __nv_bfloat162 u0 = __floats2bfloat162_rn(
                        c[0] - __bfloat162float(t0.x), c[1] - __bfloat162float(t0.y));
                    __nv_bfloat162 u1 = __floats2bfloat162_rn(
                        c[2] - __bfloat162float(t1.x), c[3] - __bfloat162float(t1.y));
                    P0[mf][half * 2 + 0] = *(uint32_t*)&t0;    // a0/a2
                    P0[mf][half * 2 + 1] = *(uint32_t*)&t1;    // a1/a3
                    P1[mf][half * 2 + 0] = *(uint32_t*)&u0;
                    P1[mf][half * 2 + 1] = *(uint32_t*)&u1;
                }
            }
#pragma unroll
            for (int dnp = 0; dnp < 4; ++dnp) {
                uint32_t V0[4], V1[4];
                const uint32_t va = kvs + 2 * ATILE
                    + (wn * 64 + kch * 16 + ((lane >> 4) & 1) * 8 + (lane & 7)) * 144
                    + dnp * 32 + ((lane >> 3) & 1) * 16;
                ldsm4t(V0, va);
                ldsm4t(V1, va + ATILE);
#pragma unroll
                for (int mf = 0; mf < 2; ++mf) {
                    hmma(O[mf][2 * dnp + 0], P0[mf], V0[0], V0[2]);   // p0 v0
                    hmma(O[mf][2 * dnp + 1], P0[mf], V0[1], V0[3]);
                    hmma(O[mf][2 * dnp + 0], P0[mf], V1[0], V1[2]);   // p0 v1
                    hmma(O[mf][2 * dnp + 1], P0[mf], V1[1], V1[3]);
                    hmma(O[mf][2 * dnp + 0], P1[mf], V0[0], V0[2]);   // p1 v0
                    hmma(O[mf][2 * dnp + 1], P1[mf], V0[1], V0[3]);
                }
            }
        }
        __syncthreads();
        if (s + 2 < 16) load_kv(s + 2);
    }

    // ---- epilogue: reduce across wn, divide by l, write 2-limb bf16 ctx ----
    __syncthreads();
    float* osm = (float*)smem;     // [128][64]
    if (wn == 1) {
#pragma unroll
        for (int mf = 0; mf < 2; ++mf)
#pragma unroll
            for (int rh = 0; rh < 2; ++rh) {
                const int row = wm * 32 + mf * 16 + rh * 8 + rloc;
#pragma unroll
                for (int dn = 0; dn < 8; ++dn) {
                    const int col = dn * 8 + (lane & 3) * 2;
                    *(float2*)(osm + row * 64 + col) =
                        make_float2(O[mf][dn][rh * 2 + 0], O[mf][dn][rh * 2 + 1]);
                }
            }
    }
    __syncthreads();
    if (wn == 0) {
#pragma unroll
        for (int mf = 0; mf < 2; ++mf)
#pragma unroll
            for (int rh = 0; rh < 2; ++rh) {
                const int sl  = mf * 2 + rh;
                const int row = wm * 32 + mf * 16 + rh * 8 + rloc;
                const float inv = 1.0f / lst[sl];
                const size_t obase = hb + (size_t)(q0r + row) * HH;
#pragma unroll
                for (int dn = 0; dn < 8; ++dn) {
                    const int col = dn * 8 + (lane & 3) * 2;
                    float2 ov = *(float2*)(osm + row * 64 + col);
                    float x = (O[mf][dn][rh * 2 + 0] + ov.x) * inv;
                    float y = (O[mf][dn][rh * 2 + 1] + ov.y) * inv;
                    __nv_bfloat162 h0 = __floats2bfloat162_rn(x, y);
                    __nv_bfloat162 g0 = __floats2bfloat162_rn(
                        x - __bfloat162float(h0.x), y - __bfloat162float(h0.y));
                    *(uint32_t*)(cx0 + obase + col) = *(uint32_t*)&h0;
                    *(uint32_t*)(cx1 + obase + col) = *(uint32_t*)&g0;
                }
            }
    }
}

// ---------------------------------------------------------------------------
// Launch
// ---------------------------------------------------------------------------
extern "C" void kernel_launch(void* const* d_in, const int* in_sizes, int n_in,
                              void* d_out, int out_size)
{
    const float* hs  = (const float*)d_in[0];
    const float* msk = (const float*)d_in[1];
    const float* q_s = (const float*)d_in[2];
    const float* q_d = (const float*)d_in[3];
    const float* k_s = (const float*)d_in[4];
    const float* k_d = (const float*)d_in[5];
    const float* v_s = (const float*)d_in[6];
    const float* v_d = (const float*)d_in[7];
    const float* o_s = (const float*)d_in[8];
    const float* o_d = (const float*)d_in[9];
    float* out = (float*)d_out;

    void* p;
    cudaGetSymbolAddress(&p, g_hs);  bf16* hsL = (bf16*)p;
    cudaGetSymbolAddress(&p, g_wsp); bf16* wsp = (bf16*)p;
    cudaGetSymbolAddress(&p, g_qkv); bf16* qkv = (bf16*)p;
    cudaGetSymbolAddress(&p, g_cx);  bf16* cxL = (bf16*)p;

    const size_t AE = (size_t)MM * HH;
    const size_t WE = (size_t)HH * HH;
    bf16 *hs0 = hsL, *hs1 = hsL + AE, *hs2 = hsL + 2 * AE;
    bf16 *wq0 = wsp,          *wq1 = wsp + WE,      *wq2 = wsp + 2 * WE;
    bf16 *wk0 = wsp + 3 * WE, *wk1 = wsp + 4 * WE,  *wk2 = wsp + 5 * WE;
    bf16 *wv0 = wsp + 6 * WE, *wv1 = wsp + 7 * WE,  *wv2 = wsp + 8 * WE;
    bf16 *wo0 = wsp + 9 * WE, *wo1 = wsp + 10 * WE, *wo2 = wsp + 11 * WE;
    bf16 *pq0 = qkv,          *pq1 = qkv + AE;
    bf16 *pk0 = qkv + 2 * AE, *pk1 = qkv + 3 * AE;
    bf16 *pv0 = qkv + 4 * AE, *pv1 = qkv + 5 * AE;
    bf16 *cx0 = cxL,          *cx1 = cxL + AE;

    // Limb splits
    split_dual3<<<(int)(AE / 4 / 256), 256>>>((const float4*)hs, nullptr,
                                              hs0, hs1, hs2, (int)(AE / 4));
    split_dual3<<<(int)(WE / 4 / 256), 256>>>((const float4*)q_s, (const float4*)q_d,
                                              wq0, wq1, wq2, (int)(WE / 4));
    split_dual3<<<(int)(WE / 4 / 256), 256>>>((const float4*)k_s, (const float4*)k_d,
                                              wk0, wk1, wk2, (int)(WE / 4));
    split_dual3<<<(int)(WE / 4 / 256), 256>>>((const float4*)v_s, (const float4*)v_d,
                                              wv0, wv1, wv2, (int)(WE / 4));
    split_dual3<<<(int)(WE / 4 / 256), 256>>>((const float4*)o_s, (const float4*)o_d,
                                              wo0, wo1, wo2, (int)(WE / 4));

    // Projection GEMMs (Q,K: 3-limb inputs; V: 2-limb) -> 2-limb bf16 outputs
    const int SMEM3 = 2 * 6 * 10240;
    const int SMEM2 = 2 * 4 * 10240;
    cudaFuncSetAttribute(mma_gemm<3, true>,  cudaFuncAttributeMaxDynamicSharedMemorySize, SMEM3);
    cudaFuncSetAttribute(mma_gemm<2, true>,  cudaFuncAttributeMaxDynamicSharedMemorySize, SMEM2);
    cudaFuncSetAttribute(mma_gemm<2, false>, cudaFuncAttributeMaxDynamicSharedMemorySize, SMEM2);
    dim3 gg(HH / 128, MM / 128);

    mma_gemm<3, true><<<gg, 256, SMEM3>>>(hs0, hs1, hs2, wq0, wq1, wq2,
                                          nullptr, pq0, pq1);
    mma_gemm<3, true><<<gg, 256, SMEM3>>>(hs0, hs1, hs2, wk0, wk1, wk2,
                                          nullptr, pk0, pk1);
    mma_gemm<2, true><<<gg, 256, SMEM2>>>(hs0, hs1, nullptr, wv0, wv1, nullptr,
                                          nullptr, pv0, pv1);

    // Attention
    const int attn_smem = 2 * ASTAGE + 2 * ATILE + 2048;   // 186368
    cudaFuncSetAttribute(attn_mma, cudaFuncAttributeMaxDynamicSharedMemorySize,
                         attn_smem);
    dim3 agrid(SS / 128, NHH, BB);
    attn_mma<<<agrid, 256, attn_smem>>>(pq0, pq1, pk0, pk1, pv0, pv1, msk,
                                        cx0, cx1);

    // O projection (ctx limbs already produced by attention)
    mma_gemm<2, false><<<gg, 256, SMEM2>>>(cx0, cx1, nullptr, wo0, wo1, nullptr,
                                           out, nullptr, nullptr);
}

// round 7
// speedup vs baseline: 4.3657x; 1.0242x over previous
#include <cuda_runtime.h>
#include <cuda_bf16.h>
#include <math.h>
#include <stdint.h>

// Problem constants
#define BB   2
#define SS   2048
#define HH   1024
#define NHH  16
#define HDD  64
#define MM   (BB * SS)          // 4096 rows

typedef __nv_bfloat16 bf16;

// ---------------------------------------------------------------------------
// Scratch (device globals: allocation-free contract)
// ---------------------------------------------------------------------------
__device__ __align__(256) bf16 g_hs[3][MM * HH];
__device__ __align__(256) bf16 g_wsp[12][HH * HH];
__device__ __align__(256) bf16 g_qkv[6][MM * HH];   // q0,q1,k0,k1,v0,v1
__device__ __align__(256) bf16 g_cx[2][MM * HH];    // ctx limbs

// ---------------------------------------------------------------------------
// Limb splits
// ---------------------------------------------------------------------------
__device__ __forceinline__ void split3_body(
    float4 a, bf16* L0, bf16* L1, bf16* L2, size_t i)
{
    float v[4] = {a.x, a.y, a.z, a.w};
    __align__(8) bf16 o0[4], o1[4], o2[4];
#pragma unroll
    for (int t = 0; t < 4; ++t) {
        float x = v[t];
        bf16 c0 = __float2bfloat16(x);
        float r = x - __bfloat162float(c0);
        bf16 c1 = __float2bfloat16(r);
        r -= __bfloat162float(c1);
        bf16 c2 = __float2bfloat16(r);
        o0[t] = c0; o1[t] = c1; o2[t] = c2;
    }
    *(uint2*)(L0 + 4 * i) = *(uint2*)o0;
    *(uint2*)(L1 + 4 * i) = *(uint2*)o1;
    *(uint2*)(L2 + 4 * i) = *(uint2*)o2;
}

__global__ void __launch_bounds__(256) split_hs(
    const float4* __restrict__ A,
    bf16* __restrict__ L0, bf16* __restrict__ L1, bf16* __restrict__ L2, int n4)
{
    int i = blockIdx.x * 256 + threadIdx.x;
    if (i >= n4) return;
    split3_body(A[i], L0, L1, L2, (size_t)i);
}

struct WSplitArgs {
    const float4* a[4];
    const float4* b[4];
    bf16 *l0[4], *l1[4], *l2[4];
};

__global__ void __launch_bounds__(256) split_w4(WSplitArgs args, int n4)
{
    const int t = blockIdx.y;
    int i = blockIdx.x * 256 + threadIdx.x;
    if (i >= n4) return;
    float4 a = args.a[t][i];
    float4 b = args.b[t][i];
    a.x += b.x; a.y += b.y; a.z += b.z; a.w += b.w;
    split3_body(a, args.l0[t], args.l1[t], args.l2[t], (size_t)i);
}

// ---------------------------------------------------------------------------
// mma.sync helpers
// ---------------------------------------------------------------------------
__device__ __forceinline__ void ldsm4(uint32_t* r, uint32_t addr) {
    asm volatile("ldmatrix.sync.aligned.m8n8.x4.shared.b16 {%0,%1,%2,%3}, [%4];"
                 : "=r"(r[0]), "=r"(r[1]), "=r"(r[2]), "=r"(r[3]) : "r"(addr));
}
__device__ __forceinline__ void ldsm4t(uint32_t* r, uint32_t addr) {
    asm volatile("ldmatrix.sync.aligned.m8n8.x4.trans.shared.b16 {%0,%1,%2,%3}, [%4];"
                 : "=r"(r[0]), "=r"(r[1]), "=r"(r[2]), "=r"(r[3]) : "r"(addr));
}
__device__ __forceinline__ void hmma(float* c, const uint32_t* a,
                                     uint32_t b0, uint32_t b1) {
    asm volatile(
        "mma.sync.aligned.m16n8k16.row.col.f32.bf16.bf16.f32 "
        "{%0,%1,%2,%3}, {%4,%5,%6,%7}, {%8,%9}, {%0,%1,%2,%3};"
        : "+f"(c[0]), "+f"(c[1]), "+f"(c[2]), "+f"(c[3])
        : "r"(a[0]), "r"(a[1]), "r"(a[2]), "r"(a[3]), "r"(b0), "r"(b1));
}

// ---------------------------------------------------------------------------
// HMMA multi-limb GEMM: 3-stage cp.async pipeline, ONE barrier per stage.
// 128x128 block tile, 8 warps (2x4), warp 64x32, K-stage 32.
// ---------------------------------------------------------------------------
template <int NL, bool LIMB>
__global__ void __launch_bounds__(256) mma_gemm(
    const bf16* __restrict__ a0, const bf16* __restrict__ a1,
    const bf16* __restrict__ a2,
    const bf16* __restrict__ b0, const bf16* __restrict__ b1,
    const bf16* __restrict__ b2,
    float* __restrict__ C, bf16* __restrict__ L0, bf16* __restrict__ L1)
{
    constexpr int NT     = 2 * NL;
    constexpr int TILEB  = 128 * 80;
    constexpr int STAGEB = NT * TILEB;

    extern __shared__ __align__(128) char smem[];
    const uint32_t sb = (uint32_t)__cvta_generic_to_shared(smem);

    const int tid  = threadIdx.x;
    const int lane = tid & 31;
    const int wid  = tid >> 5;
    const int wm   = wid >> 2;
    const int wn   = wid & 3;
    const int m0   = blockIdx.y * 128;
    const int n0   = blockIdx.x * 128;

    const bf16* srcs[NT];
    srcs[0] = a0 + (size_t)m0 * 1024;
    srcs[1] = a1 + (size_t)m0 * 1024;
    if constexpr (NL == 3) {
        srcs[2] = a2 + (size_t)m0 * 1024;
        srcs[3] = b0 + (size_t)n0 * 1024;
        srcs[4] = b1 + (size_t)n0 * 1024;
        srcs[5] = b2 + (size_t)n0 * 1024;
    } else {
        srcs[2] = b0 + (size_t)n0 * 1024;
        srcs[3] = b1 + (size_t)n0 * 1024;
    }

    auto load_stage = [&](int s) {
        const int k0 = s * 32;
        const uint32_t dstb = sb + (s % 3) * STAGEB;
#pragma unroll
        for (int t = 0; t < NT; ++t) {
#pragma unroll
            for (int i = 0; i < 2; ++i) {
                const int idx = tid + 256 * i;
                const int row = idx >> 2;
                const int ch  = idx & 3;
                uint32_t dst = dstb + t * TILEB + row * 80 + ch * 16;
                const void* src = srcs[t] + (size_t)row * 1024 + k0 + ch * 8;
                asm volatile("cp.async.cg.shared.global [%0], [%1], 16;"
                             :: "r"(dst), "l"(src) : "memory");
            }
        }
        asm volatile("cp.async.commit_group;" ::: "memory");
    };

    const uint32_t aoff = (uint32_t)((wm * 64 + (lane & 15)) * 80 + ((lane >> 4) & 1) * 16);
    const uint32_t boff = (uint32_t)((wn * 32 + ((lane >> 4) & 1) * 8 + (lane & 7)) * 80
                                     + ((lane >> 3) & 1) * 16);

    float acc[4][4][4];
#pragma unroll
    for (int mf = 0; mf < 4; ++mf)
#pragma unroll
        for (int nf = 0; nf < 4; ++nf)
#pragma unroll
            for (int r = 0; r < 4; ++r) acc[mf][nf][r] = 0.0f;

    load_stage(0);
    load_stage(1);

    for (int s = 0; s < 32; ++s) {
        if (s < 31) asm volatile("cp.async.wait_group 1;" ::: "memory");
        else        asm volatile("cp.async.wait_group 0;" ::: "memory");
        __syncthreads();
        if (s + 2 < 32) load_stage(s + 2);   // buf (s+2)%3: readers done at barrier

        const uint32_t st = sb + (s % 3) * STAGEB;
#pragma unroll
        for (int kh = 0; kh < 2; ++kh) {
            const uint32_t kB = (uint32_t)(kh * 32);
            uint32_t Af[NL][4][4];
            uint32_t Bf[NL][2][4];
#pragma unroll
            for (int l = 0; l < NL; ++l) {
#pragma unroll
                for (int mf = 0; mf < 4; ++mf)
                    ldsm4(Af[l][mf], st + l * TILEB + aoff + mf * 16 * 80 + kB);
#pragma unroll
                for (int pr = 0; pr < 2; ++pr)
                    ldsm4(Bf[l][pr], st + (NL + l) * TILEB + boff + pr * 16 * 80 + kB);
            }
#pragma unroll
            for (int i = 0; i < NL; ++i)
#pragma unroll
                for (int j = 0; j < NL; ++j) {
                    if (i + j >= NL) continue;
#pragma unroll
                    for (int mf = 0; mf < 4; ++mf)
#pragma unroll
                        for (int pr = 0; pr < 2; ++pr) {
                            hmma(acc[mf][pr * 2 + 0], Af[i][mf], Bf[j][pr][0], Bf[j][pr][1]);
                            hmma(acc[mf][pr * 2 + 1], Af[i][mf], Bf[j][pr][2], Bf[j][pr][3]);
                        }
                }
        }
    }

    const int mrow = m0 + wm * 64 + (lane >> 2);
    const int ncol = n0 + wn * 32 + (lane & 3) * 2;
#pragma unroll
    for (int mf = 0; mf < 4; ++mf)
#pragma unroll
        for (int nf = 0; nf < 4; ++nf) {
            const size_t r0 = (size_t)(mrow + mf * 16) * 1024 + ncol + nf * 8;
            const size_t r1 = r0 + 8 * 1024;
            if constexpr (LIMB) {
                float v0 = acc[mf][nf][0], v1 = acc[mf][nf][1];
                float v2 = acc[mf][nf][2], v3 = acc[mf][nf][3];
                __nv_bfloat162 h0 = __floats2bfloat162_rn(v0, v1);
                __nv_bfloat162 g0 = __floats2bfloat162_rn(
                    v0 - __bfloat162float(h0.x), v1 - __bfloat162float(h0.y));
                __nv_bfloat162 h1 = __floats2bfloat162_rn(v2, v3);
                __nv_bfloat162 g1 = __floats2bfloat162_rn(
                    v2 - __bfloat162float(h1.x), v3 - __bfloat162float(h1.y));
                *(uint32_t*)(L0 + r0) = *(uint32_t*)&h0;
                *(uint32_t*)(L1 + r0) = *(uint32_t*)&g0;
                *(uint32_t*)(L0 + r1) = *(uint32_t*)&h1;
                *(uint32_t*)(L1 + r1) = *(uint32_t*)&g1;
            } else {
                *(float2*)(C + r0) = make_float2(acc[mf][nf][0], acc[mf][nf][1]);
                *(float2*)(C + r1) = make_float2(acc[mf][nf][2], acc[mf][nf][3]);
            }
        }
}

// ---------------------------------------------------------------------------
// HMMA flash attention v2: split K/V prefetch, single-pass softmax merge,
// 2 barriers per k-iteration.
// Block = (q-tile 128, h, b). 8 warps: wm 0..3 (32 rows), wn 0..1 (64 cols).
// ---------------------------------------------------------------------------
#define ATILE  18432          // 128 rows * 144B
#define KSTAGE (2 * ATILE)    // 2 limbs

__global__ void __launch_bounds__(256, 1) attn_mma(
    const bf16* __restrict__ q0l, const bf16* __restrict__ q1l,
    const bf16* __restrict__ k0l, const bf16* __restrict__ k1l,
    const bf16* __restrict__ v0l, const bf16* __restrict__ v1l,
    const float* __restrict__ mask,
    bf16* __restrict__ cx0, bf16* __restrict__ cx1)
{
    extern __shared__ __align__(128) char smem[];
    const uint32_t sb = (uint32_t)__cvta_generic_to_shared(smem);
    const uint32_t kK   = sb;                        // K: 2 stages x 2 limbs
    const uint32_t kV   = sb + 2 * KSTAGE;           // V: 2 stages x 2 limbs
    const uint32_t qbse = sb + 4 * KSTAGE;           // Q: 2 limbs
    float* red = (float*)(smem + 4 * KSTAGE + 2 * ATILE);  // [2][128][2] (m,l)

    const int tid  = threadIdx.x;
    const int lane = tid & 31;
    const int wid  = tid >> 5;
    const int wm   = wid >> 1;
    const int wn   = wid & 1;
    const int qt = blockIdx.x, h = blockIdx.y, b = blockIdx.z;
    const int q0r = qt * 128;

    const size_t hb = (size_t)b * SS * HH + (size_t)h * HDD;
    const bf16* qsrc[2] = {q0l + hb + (size_t)q0r * HH, q1l + hb + (size_t)q0r * HH};
    const bf16* ksrc[2] = {k0l + hb, k1l + hb};
    const bf16* vsrc[2] = {v0l + hb, v1l + hb};
    const float* maskb = mask + (size_t)b * SS * SS;

    auto load_k = [&](int s) {
        const int k00 = s * 128;
        const uint32_t dstb = kK + (s & 1) * KSTAGE;
#pragma unroll
        for (int i = 0; i < 8; ++i) {
            const int idx = tid + 256 * i;
            const int limb = idx >> 10;
            const int rem  = idx & 1023;
            const int r = rem >> 3, c = rem & 7;
            uint32_t dst = dstb + limb * ATILE + r * 144 + c * 16;
            const void* src = ksrc[limb] + (size_t)(k00 + r) * HH + c * 8;
            asm volatile("cp.async.cg.shared.global [%0], [%1], 16;"
                         :: "r"(dst), "l"(src) : "memory");
        }
    };
    auto load_v = [&](int s) {
        const int k00 = s * 128;
        const uint32_t dstb = kV + (s & 1) * KSTAGE;
#pragma unroll
        for (int i = 0; i < 8; ++i) {
            const int idx = tid + 256 * i;
            const int limb = idx >> 10;
            const int rem  = idx & 1023;
            const int r = rem >> 3, c = rem & 7;
            uint32_t dst = dstb + limb * ATILE + r * 144 + c * 16;
            const void* src = vsrc[limb] + (size_t)(k00 + r) * HH + c * 8;
            asm volatile("cp.async.cg.shared.global [%0], [%1], 16;"
                         :: "r"(dst), "l"(src) : "memory");
        }
    };

    // Prologue: G0 = {Q, K0, V0}; G1 = {K1}
#pragma unroll
    for (int i = 0; i < 8; ++i) {
        const int idx = tid + 256 * i;
        const int limb = idx >> 10;
        const int rem  = idx & 1023;
        const int r = rem >> 3, c = rem & 7;
        uint32_t dst = qbse + limb * ATILE + r * 144 + c * 16;
        const void* src = qsrc[limb] + (size_t)r * HH + c * 8;
        asm volatile("cp.async.cg.shared.global [%0], [%1], 16;"
                     :: "r"(dst), "l"(src) : "memory");
    }
    load_k(0);
    load_v(0);
    asm volatile("cp.async.commit_group;" ::: "memory");
    load_k(1);
    asm volatile("cp.async.commit_group;" ::: "memory");

    float O[2][8][4];
#pragma unroll
    for (int mf = 0; mf < 2; ++mf)
#pragma unroll
        for (int dn = 0; dn < 8; ++dn)
#pragma unroll
            for (int r = 0; r < 4; ++r) O[mf][dn][r] = 0.0f;
    float mst[4] = {-INFINITY, -INFINITY, -INFINITY, -INFINITY};
    float lst[4] = {0.0f, 0.0f, 0.0f, 0.0f};

    const int rloc = (lane >> 2);
    const float scale = 0.125f;

    for (int s = 0; s < 16; ++s) {
        // need V(s) done; only K(s+1) group may still be pending
        if (s < 15) asm volatile("cp.async.wait_group 1;" ::: "memory");
        else        asm volatile("cp.async.wait_group 0;" ::: "memory");
        __syncthreads();                              // barrier A

        // V(s+1): its buffer's readers (PV of s-1) all passed barrier A
        if (s + 1 < 16) {
            load_v(s + 1);
            asm volatile("cp.async.commit_group;" ::: "memory");
        }

        const uint32_t kst = kK + (s & 1) * KSTAGE;
        const uint32_t vst = kV + (s & 1) * KSTAGE;

        // prefetch mask into registers (hidden under QK)
        float2 mreg[2][8];
#pragma unroll
        for (int mf = 0; mf < 2; ++mf)
#pragma unroll
            for (int rh = 0; rh < 2; ++rh) {
                const int row = q0r + wm * 32 + mf * 16 + rh * 8 + rloc;
                const float* mrp = maskb + (size_t)row * SS + s * 128 + wn * 64
                                   + (lane & 3) * 2;
#pragma unroll
                for (int nf2 = 0; nf2 < 4; ++nf2)
                    mreg[mf][rh * 4 + nf2] = *(const float2*)(mrp + (rh * 4 + nf2) * 0
                                              + 0);   // placeholder, fixed below
            }
        // NOTE: correct mask addressing done inline below (mreg filled properly)
#pragma unroll
        for (int mf = 0; mf < 2; ++mf)
#pragma unroll
            for (int rh = 0; rh < 2; ++rh) {
                const int row = q0r + wm * 32 + mf * 16 + rh * 8 + rloc;
                const float* mrp = maskb + (size_t)row * SS + s * 128 + wn * 64
                                   + (lane & 3) * 2;
#pragma unroll
                for (int nf = 0; nf < 8; ++nf)
                    if ((nf & 1) == 0 ? true : true) { }
                // fill: mreg[mf][rh*?]: we need 8 nf values per (mf,rh) pair but
                // mreg is [2][8]: index [mf][nf] holds rh pair? Use layout below.
            }

        // ---- QK^T ----
        float S[2][8][4];
#pragma unroll
        for (int mf = 0; mf < 2; ++mf)
#pragma unroll
            for (int nf = 0; nf < 8; ++nf)
#pragma unroll
                for (int r = 0; r < 4; ++r) S[mf][nf][r] = 0.0f;

#pragma unroll
        for (int ch = 0; ch < 4; ++ch) {
            uint32_t A[2][2][4];
#pragma unroll
            for (int l = 0; l < 2; ++l)
#pragma unroll
                for (int mf = 0; mf < 2; ++mf)
                    ldsm4(A[l][mf], qbse + l * ATILE
                          + (wm * 32 + mf * 16 + (lane & 15)) * 144
                          + ch * 32 + ((lane >> 4) & 1) * 16);
#pragma unroll
            for (int bp = 0; bp < 4; ++bp) {
                uint32_t B0[4], B1[4];
                const uint32_t ba = kst
                    + (wn * 64 + bp * 16 + ((lane >> 4) & 1) * 8 + (lane & 7)) * 144
                    + ((lane >> 3) & 1) * 16 + ch * 32;
                ldsm4(B0, ba);
                ldsm4(B1, ba + ATILE);
#pragma unroll
                for (int mf = 0; mf < 2; ++mf) {
                    hmma(S[mf][2 * bp + 0], A[0][mf], B0[0], B0[1]);
                    hmma(S[mf][2 * bp + 1], A[0][mf], B0[2], B0[3]);
                    hmma(S[mf][2 * bp + 0], A[0][mf], B1[0], B1[1]);
                    hmma(S[mf][2 * bp + 1], A[0][mf], B1[2], B1[3]);
                    hmma(S[mf][2 * bp + 0], A[1][mf], B0[0], B0[1]);
                    hmma(S[mf][2 * bp + 1], A[1][mf], B0[2], B0[3]);
                }
            }
        }

        // ---- scale + mask + local max ----
        float mloc[4] = {-INFINITY, -INFINITY, -INFINITY, -INFINITY};
#pragma unroll
        for (int mf = 0; mf < 2; ++mf)
#pragma unroll
            for (int rh = 0; rh < 2; ++rh) {
                const int row = q0r + wm * 32 + mf * 16 + rh * 8 + rloc;
                const float* mrp = maskb + (size_t)row * SS + s * 128 + wn * 64
                                   + (lane & 3) * 2;
                const int sl = mf * 2 + rh;
#pragma unroll
                for (int nf = 0; nf < 8; ++nf) {
                    float2 mv = *(const float2*)(mrp + nf * 8);
                    float a = fmaf(S[mf][nf][rh * 2 + 0], scale, mv.x);
                    float c = fmaf(S[mf][nf][rh * 2 + 1], scale, mv.y);
                    S[mf][nf][rh * 2 + 0] = a;
                    S[mf][nf][rh * 2 + 1] = c;
                    mloc[sl] = fmaxf(mloc[sl], fmaxf(a, c));
                }
            }
#pragma unroll
        for (int off = 1; off < 4; off <<= 1)
#pragma unroll
            for (int sl = 0; sl < 4; ++sl)
                mloc[sl] = fmaxf(mloc[sl], __shfl_xor_sync(0xffffffffu, mloc[sl], off));

        // ---- exp with LOCAL max + local sum (pre-barrier) ----
        float lw[4];
#pragma unroll
        for (int mf = 0; mf < 2; ++mf)
#pragma unroll
            for (int rh = 0; rh < 2; ++rh) {
                const int sl = mf * 2 + rh;
                float ls = 0.0f;
#pragma unroll
                for (int nf = 0; nf < 8; ++nf) {
                    float a = __expf(S[mf][nf][rh * 2 + 0] - mloc[sl]);
                    float c = __expf(S[mf][nf][rh * 2 + 1] - mloc[sl]);
                    S[mf][nf][rh * 2 + 0] = a;
                    S[mf][nf][rh * 2 + 1] = c;
                    ls += a + c;
                }
                lw[sl] = ls;
            }
#pragma unroll
        for (int off = 1; off < 4; off <<= 1)
#pragma unroll
            for (int sl = 0; sl < 4; ++sl)
                lw[sl] += __shfl_xor_sync(0xffffffffu, lw[sl], off);

        if ((lane & 3) == 0) {
#pragma unroll
            for (int mf = 0; mf < 2; ++mf)
#pragma unroll
                for (int rh = 0; rh < 2; ++rh) {
                    const int rr = wm * 32 + mf * 16 + rh * 8 + rloc;
                    red[wn * 256 + rr * 2 + 0] = mloc[mf * 2 + rh];
                    red[wn * 256 + rr * 2 + 1] = lw[mf * 2 + rh];
                }
        }
        __syncthreads();                              // barrier B

        // K(s+2): all warps finished QK reads of K buf s%2 at barrier B
        if (s + 2 < 16) {
            load_k(s + 2);
            asm volatile("cp.async.commit_group;" ::: "memory");
        }

        // ---- cross-half merge ----
        float alpha[4], beta[4];
#pragma unroll
        for (int mf = 0; mf < 2; ++mf)
#pragma unroll
            for (int rh = 0; rh < 2; ++rh) {
                const int sl = mf * 2 + rh;
                const int rr = wm * 32 + mf * 16 + rh * 8 + rloc;
                const float mp = red[(wn ^ 1) * 256 + rr * 2 + 0];
                const float lp = red[(wn ^ 1) * 256 + rr * 2 + 1];
                const float mnew = fmaxf(mst[sl], fmaxf(mloc[sl], mp));
                alpha[sl] = __expf(mst[sl] - mnew);
                beta[sl]  = __expf(mloc[sl] - mnew);
                lst[sl] = lst[sl] * alpha[sl] + lw[sl] * beta[sl]
                          + lp * __expf(mp - mnew);
                mst[sl] = mnew;
            }
#pragma unroll
        for (int mf = 0; mf < 2; ++mf)
#pragma unroll
            for (int dn = 0; dn < 8; ++dn) {
                O[mf][dn][0] *= alpha[mf * 2 + 0];
                O[mf][dn][1] *= alpha[mf * 2 + 0];
                O[mf][dn][2] *= alpha[mf * 2 + 1];
                O[mf][dn][3] *= alpha[mf * 2 + 1];
            }

        // ---- PV (P scaled by beta during frag build) ----
#pragma unroll
        for (int kch = 0; kch < 4; ++kch) {
            uint32_t P0[2][4], P1[2][4];
#pragma unroll
            for (int mf = 0; mf < 2; ++mf) {
                const float b0s = beta[mf * 2 + 0];
                const float b1s = beta[mf * 2 + 1];
#pragma unroll
                for (int half = 0; half < 2; ++half) {
                    const float* c = S[mf][2 * kch + half];
                    float x0 = c[0] * b0s, x1 = c[1] * b0s;
                    float x2 = c[2] * b1s, x3 = c[3] * b1s;
                    __nv_bfloat162 t0 = __floats2bfloat162_rn(x0, x1);
                    __nv_bfloat162 t1 = __floats2bfloat162_rn(x2, x3);
                    __nv_bfloat162 u0 = __floats2bfloat162_rn(
                        x0 - __bfloat162float(t0.x), x1 - __bfloat162float(t0.y));
                    __nv_bfloat162 u1 = __floats2bfloat162_rn(
                        x2 - __bfloat162float(t1.x), x3 - __bfloat162float(t1.y));
                    P0[mf][half * 2 + 0] = *(uint32_t*)&t0;
                    P0[mf][half * 2 + 1] = *(uint32_t*)&t1;
                    P1[mf][half * 2 + 0] = *(uint32_t*)&u0;
                    P1[mf][half * 2 + 1] = *(uint32_t*)&u1;
                }
            }
#pragma unroll
            for (int dnp = 0; dnp < 4; ++dnp) {
                uint32_t V0[4], V1[4];
                const uint32_t va = vst
                    + (wn * 64 + kch * 16 + ((lane >> 4) & 1) * 8 + (lane & 7)) * 144
                    + dnp * 32 + ((lane >> 3) & 1) * 16;
                ldsm4t(V0, va);
                ldsm4t(V1, va + ATILE);
#pragma unroll
                for (int mf = 0; mf < 2; ++mf) {
                    hmma(O[mf][2 * dnp + 0], P0[mf], V0[0], V0[2]);
                    hmma(O[mf][2 * dnp + 1], P0[mf], V0[1], V0[3]);
                    hmma(O[mf][2 * dnp + 0], P0[mf], V1[0], V1[2]);
                    hmma(O[mf][2 * dnp + 1], P0[mf], V1[1], V1[3]);
                    hmma(O[mf][2 * dnp + 0], P1[mf], V0[0], V0[2]);
                    hmma(O[mf][2 * dnp + 1], P1[mf], V0[1], V0[3]);
                }
            }
        }
        // no end barrier: next iter's barrier A protects V buffer reuse
    }

    // ---- epilogue: reduce across wn, normalize, write 2-limb bf16 ctx ----
    __syncthreads();
    float* osm = (float*)smem;     // [128][64]
    if (wn == 1) {
#pragma unroll
        for (int mf = 0; mf < 2; ++mf)
#pragma unroll
            for (int rh = 0; rh < 2; ++rh) {
                const int row = wm * 32 + mf * 16 + rh * 8 + rloc;
#pragma unroll
                for (int dn = 0; dn < 8; ++dn) {
                    const int col = dn * 8 + (lane & 3) * 2;
                    *(float2*)(osm + row * 64 + col) =
                        make_float2(O[mf][dn][rh * 2 + 0], O[mf][dn][rh * 2 + 1]);
                }
            }
    }
    __syncthreads();
    if (wn == 0) {
#pragma unroll
        for (int mf = 0; mf < 2; ++mf)
#pragma unroll
            for (int rh = 0; rh < 2; ++rh) {
                const int sl  = mf * 2 + rh;
                const int row = wm * 32 + mf * 16 + rh * 8 + rloc;
                const float inv = 1.0f / lst[sl];
                const size_t obase = hb + (size_t)(q0r + row) * HH;
#pragma unroll
                for (int dn = 0; dn < 8; ++dn) {
                    const int col = dn * 8 + (lane & 3) * 2;
                    float2 ov = *(float2*)(osm + row * 64 + col);
                    float x = (O[mf][dn][rh * 2 + 0] + ov.x) * inv;
                    float y = (O[mf][dn][rh * 2 + 1] + ov.y) * inv;
                    __nv_bfloat162 h0 = __floats2bfloat162_rn(x, y);
                    __nv_bfloat162 g0 = __floats2bfloat162_rn(
                        x - __bfloat162float(h0.x), y - __bfloat162float(h0.y));
                    *(uint32_t*)(cx0 + obase + col) = *(uint32_t*)&h0;
                    *(uint32_t*)(cx1 + obase + col) = *(uint32_t*)&g0;
                }
            }
    }
}

// ---------------------------------------------------------------------------
// Launch
// ---------------------------------------------------------------------------
extern "C" void kernel_launch(void* const* d_in, const int* in_sizes, int n_in,
                              void* d_out, int out_size)
{
    const float* hs  = (const float*)d_in[0];
    const float* msk = (const float*)d_in[1];
    const float* q_s = (const float*)d_in[2];
    const float* q_d = (const float*)d_in[3];
    const float* k_s = (const float*)d_in[4];
    const float* k_d = (const float*)d_in[5];
    const float* v_s = (const float*)d_in[6];
    const float* v_d = (const float*)d_in[7];
    const float* o_s = (const float*)d_in[8];
    const float* o_d = (const float*)d_in[9];
    float* out = (float*)d_out;

    void* p;
    cudaGetSymbolAddress(&p, g_hs);  bf16* hsL = (bf16*)p;
    cudaGetSymbolAddress(&p, g_wsp); bf16* wsp = (bf16*)p;
    cudaGetSymbolAddress(&p, g_qkv); bf16* qkv = (bf16*)p;
    cudaGetSymbolAddress(&p, g_cx);  bf16* cxL = (bf16*)p;

    const size_t AE = (size_t)MM * HH;
    const size_t WE = (size_t)HH * HH;
    bf16 *hs0 = hsL, *hs1 = hsL + AE, *hs2 = hsL + 2 * AE;
    bf16 *wq0 = wsp,          *wq1 = wsp + WE,      *wq2 = wsp + 2 * WE;
    bf16 *wk0 = wsp + 3 * WE, *wk1 = wsp + 4 * WE,  *wk2 = wsp + 5 * WE;
    bf16 *wv0 = wsp + 6 * WE, *wv1 = wsp + 7 * WE,  *wv2 = wsp + 8 * WE;
    bf16 *wo0 = wsp + 9 * WE, *wo1 = wsp + 10 * WE, *wo2 = wsp + 11 * WE;
    bf16 *pq0 = qkv,          *pq1 = qkv + AE;
    bf16 *pk0 = qkv + 2 * AE, *pk1 = qkv + 3 * AE;
    bf16 *pv0 = qkv + 4 * AE, *pv1 = qkv + 5 * AE;
    bf16 *cx0 = cxL,          *cx1 = cxL + AE;

    // Splits: hs (1 launch) + 4 weights (1 fused launch)
    split_hs<<<(int)(AE / 4 / 256), 256>>>((const float4*)hs, hs0, hs1, hs2,
                                           (int)(AE / 4));
    WSplitArgs wa;
    wa.a[0] = (const float4*)q_s; wa.b[0] = (const float4*)q_d;
    wa.l0[0] = wq0; wa.l1[0] = wq1; wa.l2[0] = wq2;
    wa.a[1] = (const float4*)k_s; wa.b[1] = (const float4*)k_d;
    wa.l0[1] = wk0; wa.l1[1] = wk1; wa.l2[1] = wk2;
    wa.a[2] = (const float4*)v_s; wa.b[2] = (const float4*)v_d;
    wa.l0[2] = wv0; wa.l1[2] = wv1; wa.l2[2] = wv2;
    wa.a[3] = (const float4*)o_s; wa.b[3] = (const float4*)o_d;
    wa.l0[3] = wo0; wa.l1[3] = wo1; wa.l2[3] = wo2;
    split_w4<<<dim3((int)(WE / 4 / 256), 4), 256>>>(wa, (int)(WE / 4));

    // GEMMs (3-stage pipeline)
    const int SMEM3 = 3 * 6 * 10240;   // 184320
    const int SMEM2 = 3 * 4 * 10240;   // 122880
    cudaFuncSetAttribute(mma_gemm<3, true>,  cudaFuncAttributeMaxDynamicSharedMemorySize, SMEM3);
    cudaFuncSetAttribute(mma_gemm<2, true>,  cudaFuncAttributeMaxDynamicSharedMemorySize, SMEM2);
    cudaFuncSetAttribute(mma_gemm<2, false>, cudaFuncAttributeMaxDynamicSharedMemorySize, SMEM2);
    dim3 gg(HH / 128, MM / 128);

    mma_gemm<3, true><<<gg, 256, SMEM3>>>(hs0, hs1, hs2, wq0, wq1, wq2,
                                          nullptr, pq0, pq1);
    mma_gemm<3, true><<<gg, 256, SMEM3>>>(hs0, hs1, hs2, wk0, wk1, wk2,
                                          nullptr, pk0, pk1);
    mma_gemm<2, true><<<gg, 256, SMEM2>>>(hs0, hs1, nullptr, wv0, wv1, nullptr,
                                          nullptr, pv0, pv1);

    // Attention
    const int attn_smem = 4 * KSTAGE + 2 * ATILE + 2048;   // 186368
    cudaFuncSetAttribute(attn_mma, cudaFuncAttributeMaxDynamicSharedMemorySize,
                         attn_smem);
    dim3 agrid(SS / 128, NHH, BB);
    attn_mma<<<agrid, 256, attn_smem>>>(pq0, pq1, pk0, pk1, pv0, pv1, msk,
                                        cx0, cx1);

    // O projection
    mma_gemm<2, false><<<gg, 256, SMEM2>>>(cx0, cx1, nullptr, wo0, wo1, nullptr,
                                           out, nullptr, nullptr);
}

// round 11
// speedup vs baseline: 4.4729x; 1.0245x over previous
#include <cuda_runtime.h>
#include <cuda_bf16.h>
#include <math.h>
#include <stdint.h>

// Problem constants
#define BB   2
#define SS   2048
#define HH   1024
#define NHH  16
#define HDD  64
#define MM   (BB * SS)          // 4096 rows

typedef __nv_bfloat16 bf16;

// ---------------------------------------------------------------------------
// Scratch (device globals: allocation-free contract)
// ---------------------------------------------------------------------------
__device__ __align__(256) bf16 g_hs[3][MM * HH];
__device__ __align__(256) bf16 g_wsp[12][HH * HH];
__device__ __align__(256) bf16 g_qkv[6][MM * HH];   // q0,q1,k0,k1,v0,v1
__device__ __align__(256) bf16 g_cx[2][MM * HH];    // ctx limbs

// ---------------------------------------------------------------------------
// Limb splits
// ---------------------------------------------------------------------------
__device__ __forceinline__ void split3_body(
    float4 a, bf16* L0, bf16* L1, bf16* L2, size_t i)
{
    float v[4] = {a.x, a.y, a.z, a.w};
    __align__(8) bf16 o0[4], o1[4], o2[4];
#pragma unroll
    for (int t = 0; t < 4; ++t) {
        float x = v[t];
        bf16 c0 = __float2bfloat16(x);
        float r = x - __bfloat162float(c0);
        bf16 c1 = __float2bfloat16(r);
        r -= __bfloat162float(c1);
        bf16 c2 = __float2bfloat16(r);
        o0[t] = c0; o1[t] = c1; o2[t] = c2;
    }
    *(uint2*)(L0 + 4 * i) = *(uint2*)o0;
    *(uint2*)(L1 + 4 * i) = *(uint2*)o1;
    *(uint2*)(L2 + 4 * i) = *(uint2*)o2;
}

__global__ void __launch_bounds__(256) split_hs(
    const float4* __restrict__ A,
    bf16* __restrict__ L0, bf16* __restrict__ L1, bf16* __restrict__ L2, int n4)
{
    int i = blockIdx.x * 256 + threadIdx.x;
    if (i >= n4) return;
    split3_body(A[i], L0, L1, L2, (size_t)i);
}

struct WSplitArgs {
    const float4* a[4];
    const float4* b[4];
    bf16 *l0[4], *l1[4], *l2[4];
};

__global__ void __launch_bounds__(256) split_w4(WSplitArgs args, int n4)
{
    const int t = blockIdx.y;
    int i = blockIdx.x * 256 + threadIdx.x;
    if (i >= n4) return;
    float4 a = args.a[t][i];
    float4 b = args.b[t][i];
    a.x += b.x; a.y += b.y; a.z += b.z; a.w += b.w;
    split3_body(a, args.l0[t], args.l1[t], args.l2[t], (size_t)i);
}

// ---------------------------------------------------------------------------
// mma.sync helpers
// ---------------------------------------------------------------------------
__device__ __forceinline__ void ldsm4(uint32_t* r, uint32_t addr) {
    asm volatile("ldmatrix.sync.aligned.m8n8.x4.shared.b16 {%0,%1,%2,%3}, [%4];"
                 : "=r"(r[0]), "=r"(r[1]), "=r"(r[2]), "=r"(r[3]) : "r"(addr));
}
__device__ __forceinline__ void ldsm4t(uint32_t* r, uint32_t addr) {
    asm volatile("ldmatrix.sync.aligned.m8n8.x4.trans.shared.b16 {%0,%1,%2,%3}, [%4];"
                 : "=r"(r[0]), "=r"(r[1]), "=r"(r[2]), "=r"(r[3]) : "r"(addr));
}
__device__ __forceinline__ void hmma(float* c, const uint32_t* a,
                                     uint32_t b0, uint32_t b1) {
    asm volatile(
        "mma.sync.aligned.m16n8k16.row.col.f32.bf16.bf16.f32 "
        "{%0,%1,%2,%3}, {%4,%5,%6,%7}, {%8,%9}, {%0,%1,%2,%3};"
        : "+f"(c[0]), "+f"(c[1]), "+f"(c[2]), "+f"(c[3])
        : "r"(a[0]), "r"(a[1]), "r"(a[2]), "r"(a[3]), "r"(b0), "r"(b1));
}

// ---------------------------------------------------------------------------
// HMMA multi-limb GEMM, 2 CTAs/SM.
// Swizzled smem: tile = 128 rows x 64B (32 bf16), phys chunk = ch ^ ((r>>1)&3).
// 2-stage pipeline, one barrier per stage. 8 warps (2x4), warp 64x32.
// ---------------------------------------------------------------------------
template <int NL, bool LIMB>
__global__ void __launch_bounds__(256, 2) mma_gemm(
    const bf16* __restrict__ a0, const bf16* __restrict__ a1,
    const bf16* __restrict__ a2,
    const bf16* __restrict__ b0, const bf16* __restrict__ b1,
    const bf16* __restrict__ b2,
    float* __restrict__ C, bf16* __restrict__ L0, bf16* __restrict__ L1)
{
    constexpr int NT     = 2 * NL;
    constexpr int TILEB  = 128 * 64;      // 8192
    constexpr int STAGEB = NT * TILEB;

    extern __shared__ __align__(128) char smem[];
    const uint32_t sb = (uint32_t)__cvta_generic_to_shared(smem);

    const int tid  = threadIdx.x;
    const int lane = tid & 31;
    const int wid  = tid >> 5;
    const int wm   = wid >> 2;
    const int wn   = wid & 3;
    const int m0   = blockIdx.y * 128;
    const int n0   = blockIdx.x * 128;

    const bf16* srcs[NT];
    srcs[0] = a0 + (size_t)m0 * 1024;
    srcs[1] = a1 + (size_t)m0 * 1024;
    if constexpr (NL == 3) {
        srcs[2] = a2 + (size_t)m0 * 1024;
        srcs[3] = b0 + (size_t)n0 * 1024;
        srcs[4] = b1 + (size_t)n0 * 1024;
        srcs[5] = b2 + (size_t)n0 * 1024;
    } else {
        srcs[2] = b0 + (size_t)n0 * 1024;
        srcs[3] = b1 + (size_t)n0 * 1024;
    }

    auto load_stage = [&](int s) {
        const int k0 = s * 32;
        const uint32_t dstb = sb + (s & 1) * STAGEB;
#pragma unroll
        for (int i = 0; i < NT * 2; ++i) {
            const int idx = tid + 256 * i;
            const int t   = idx >> 9;              // 512 chunks per tile
            const int c   = idx & 511;
            const int row = c >> 2;
            const int ch  = c & 3;
            const uint32_t phys = (uint32_t)(row * 64 + ((ch ^ ((row >> 1) & 3)) << 4));
            uint32_t dst = dstb + t * TILEB + phys;
            const void* src = srcs[t] + (size_t)row * 1024 + k0 + ch * 8;
            asm volatile("cp.async.cg.shared.global [%0], [%1], 16;"
                         :: "r"(dst), "l"(src) : "memory");
        }
        asm volatile("cp.async.commit_group;" ::: "memory");
    };

    float acc[4][4][4];
#pragma unroll
    for (int mf = 0; mf < 4; ++mf)
#pragma unroll
        for (int nf = 0; nf < 4; ++nf)
#pragma unroll
            for (int r = 0; r < 4; ++r) acc[mf][nf][r] = 0.0f;

    load_stage(0);

    for (int s = 0; s < 32; ++s) {
        asm volatile("cp.async.wait_group 0;" ::: "memory");
        __syncthreads();
        if (s + 1 < 32) load_stage(s + 1);

        const uint32_t st = sb + (s & 1) * STAGEB;
#pragma unroll
        for (int kh = 0; kh < 2; ++kh) {
            uint32_t Af[NL][4][4];
            uint32_t Bf[NL][2][4];
#pragma unroll
            for (int l = 0; l < NL; ++l) {
#pragma unroll
                for (int mf = 0; mf < 4; ++mf) {
                    const int r  = wm * 64 + mf * 16 + (lane & 15);
                    const int ch = kh * 2 + ((lane >> 4) & 1);
                    ldsm4(Af[l][mf], st + l * TILEB
                          + r * 64 + ((ch ^ ((r >> 1) & 3)) << 4));
                }
#pragma unroll
                for (int pr = 0; pr < 2; ++pr) {
                    const int r  = wn * 32 + pr * 16 + ((lane >> 4) & 1) * 8 + (lane & 7);
                    const int ch = kh * 2 + ((lane >> 3) & 1);
                    ldsm4(Bf[l][pr], st + (NL + l) * TILEB
                          + r * 64 + ((ch ^ ((r >> 1) & 3)) << 4));
                }
            }
#pragma unroll
            for (int i = 0; i < NL; ++i)
#pragma unroll
                for (int j = 0; j < NL; ++j) {
                    if (i + j >= NL) continue;
#pragma unroll
                    for (int mf = 0; mf < 4; ++mf)
#pragma unroll
                        for (int pr = 0; pr < 2; ++pr) {
                            hmma(acc[mf][pr * 2 + 0], Af[i][mf], Bf[j][pr][0], Bf[j][pr][1]);
                            hmma(acc[mf][pr * 2 + 1], Af[i][mf], Bf[j][pr][2], Bf[j][pr][3]);
                        }
                }
        }
    }

    const int mrow = m0 + wm * 64 + (lane >> 2);
    const int ncol = n0 + wn * 32 + (lane & 3) * 2;
#pragma unroll
    for (int mf = 0; mf < 4; ++mf)
#pragma unroll
        for (int nf = 0; nf < 4; ++nf) {
            const size_t r0 = (size_t)(mrow + mf * 16) * 1024 + ncol + nf * 8;
            const size_t r1 = r0 + 8 * 1024;
            if constexpr (LIMB) {
                float v0 = acc[mf][nf][0], v1 = acc[mf][nf][1];
                float v2 = acc[mf][nf][2], v3 = acc[mf][nf][3];
                __nv_bfloat162 h0 = __floats2bfloat162_rn(v0, v1);
                __nv_bfloat162 g0 = __floats2bfloat162_rn(
                    v0 - __bfloat162float(h0.x), v1 - __bfloat162float(h0.y));
                __nv_bfloat162 h1 = __floats2bfloat162_rn(v2, v3);
                __nv_bfloat162 g1 = __floats2bfloat162_rn(
                    v2 - __bfloat162float(h1.x), v3 - __bfloat162float(h1.y));
                *(uint32_t*)(L0 + r0) = *(uint32_t*)&h0;
                *(uint32_t*)(L1 + r0) = *(uint32_t*)&g0;
                *(uint32_t*)(L0 + r1) = *(uint32_t*)&h1;
                *(uint32_t*)(L1 + r1) = *(uint32_t*)&g1;
            } else {
                *(float2*)(C + r0) = make_float2(acc[mf][nf][0], acc[mf][nf][1]);
                *(float2*)(C + r1) = make_float2(acc[mf][nf][2], acc[mf][nf][3]);
            }
        }
}

// ---------------------------------------------------------------------------
// HMMA flash attention, 512 threads (16 warps): wm=wid>>2 (32 q-rows),
// wn=wid&3 (32 k-cols). Split K/V prefetch, 4-quarter softmax merge.
// K/V/Q tiles keep the padded 144B row layout (needed for ldsm + ldsm.trans).
// ---------------------------------------------------------------------------
#define ATILE  18432          // 128 rows * 144B
#define KSTAGE (2 * ATILE)    // 2 limbs

__global__ void __launch_bounds__(512, 1) attn_mma(
    const bf16* __restrict__ q0l, const bf16* __restrict__ q1l,
    const bf16* __restrict__ k0l, const bf16* __restrict__ k1l,
    const bf16* __restrict__ v0l, const bf16* __restrict__ v1l,
    const float* __restrict__ mask,
    bf16* __restrict__ cx0, bf16* __restrict__ cx1)
{
    extern __shared__ __align__(128) char smem[];
    const uint32_t sb = (uint32_t)__cvta_generic_to_shared(smem);
    const uint32_t kK   = sb;
    const uint32_t kV   = sb + 2 * KSTAGE;
    const uint32_t qbse = sb + 4 * KSTAGE;
    float* red = (float*)(smem + 4 * KSTAGE + 2 * ATILE);   // [4][128][2]

    const int tid  = threadIdx.x;
    const int lane = tid & 31;
    const int wid  = tid >> 5;
    const int wm   = wid >> 2;          // 0..3 : 32 q-rows
    const int wn   = wid & 3;           // 0..3 : 32 k-cols
    const int qt = blockIdx.x, h = blockIdx.y, b = blockIdx.z;
    const int q0r = qt * 128;

    const size_t hb = (size_t)b * SS * HH + (size_t)h * HDD;
    const bf16* qsrc[2] = {q0l + hb + (size_t)q0r * HH, q1l + hb + (size_t)q0r * HH};
    const bf16* ksrc[2] = {k0l + hb, k1l + hb};
    const bf16* vsrc[2] = {v0l + hb, v1l + hb};
    const float* maskb = mask + (size_t)b * SS * SS;

    auto load_k = [&](int s) {
        const int k00 = s * 128;
        const uint32_t dstb = kK + (s & 1) * KSTAGE;
#pragma unroll
        for (int i = 0; i < 4; ++i) {
            const int idx = tid + 512 * i;
            const int limb = idx >> 10;
            const int rem  = idx & 1023;
            const int r = rem >> 3, c = rem & 7;
            uint32_t dst = dstb + limb * ATILE + r * 144 + c * 16;
            const void* src = ksrc[limb] + (size_t)(k00 + r) * HH + c * 8;
            asm volatile("cp.async.cg.shared.global [%0], [%1], 16;"
                         :: "r"(dst), "l"(src) : "memory");
        }
    };
    auto load_v = [&](int s) {
        const int k00 = s * 128;
        const uint32_t dstb = kV + (s & 1) * KSTAGE;
#pragma unroll
        for (int i = 0; i < 4; ++i) {
            const int idx = tid + 512 * i;
            const int limb = idx >> 10;
            const int rem  = idx & 1023;
            const int r = rem >> 3, c = rem & 7;
            uint32_t dst = dstb + limb * ATILE + r * 144 + c * 16;
            const void* src = vsrc[limb] + (size_t)(k00 + r) * HH + c * 8;
            asm volatile("cp.async.cg.shared.global [%0], [%1], 16;"
                         :: "r"(dst), "l"(src) : "memory");
        }
    };

    // Prologue: G0 = {Q, K0, V0}; G1 = {K1}
#pragma unroll
    for (int i = 0; i < 4; ++i) {
        const int idx = tid + 512 * i;
        const int limb = idx >> 10;
        const int rem  = idx & 1023;
        const int r = rem >> 3, c = rem & 7;
        uint32_t dst = qbse + limb * ATILE + r * 144 + c * 16;
        const void* src = qsrc[limb] + (size_t)r * HH + c * 8;
        asm volatile("cp.async.cg.shared.global [%0], [%1], 16;"
                     :: "r"(dst), "l"(src) : "memory");
    }
    load_k(0);
    load_v(0);
    asm volatile("cp.async.commit_group;" ::: "memory");
    load_k(1);
    asm volatile("cp.async.commit_group;" ::: "memory");

    float O[2][8][4];
#pragma unroll
    for (int mf = 0; mf < 2; ++mf)
#pragma unroll
        for (int dn = 0; dn < 8; ++dn)
#pragma unroll
            for (int r = 0; r < 4; ++r) O[mf][dn][r] = 0.0f;
    float mst[4] = {-INFINITY, -INFINITY, -INFINITY, -INFINITY};
    float lst[4] = {0.0f, 0.0f, 0.0f, 0.0f};

    const int rloc = (lane >> 2);
    const float scale = 0.125f;

    for (int s = 0; s < 16; ++s) {
        if (s < 15) asm volatile("cp.async.wait_group 1;" ::: "memory");
        else        asm volatile("cp.async.wait_group 0;" ::: "memory");
        __syncthreads();                              // barrier A

        if (s + 1 < 16) {
            load_v(s + 1);
            asm volatile("cp.async.commit_group;" ::: "memory");
        }

        const uint32_t kst = kK + (s & 1) * KSTAGE;
        const uint32_t vst = kV + (s & 1) * KSTAGE;

        // ---- QK^T over this warp's 32 cols ----
        float S[2][4][4];
#pragma unroll
        for (int mf = 0; mf < 2; ++mf)
#pragma unroll
            for (int nf = 0; nf < 4; ++nf)
#pragma unroll
                for (int r = 0; r < 4; ++r) S[mf][nf][r] = 0.0f;

#pragma unroll
        for (int ch = 0; ch < 4; ++ch) {
            uint32_t A[2][2][4];   // [limb][mf]
#pragma unroll
            for (int l = 0; l < 2; ++l)
#pragma unroll
                for (int mf = 0; mf < 2; ++mf)
                    ldsm4(A[l][mf], qbse + l * ATILE
                          + (wm * 32 + mf * 16 + (lane & 15)) * 144
                          + ch * 32 + ((lane >> 4) & 1) * 16);
            uint32_t Bq[2][2][4];  // [bp][limb]
#pragma unroll
            for (int bp = 0; bp < 2; ++bp) {
                const uint32_t ba = kst
                    + (wn * 32 + bp * 16 + ((lane >> 4) & 1) * 8 + (lane & 7)) * 144
                    + ((lane >> 3) & 1) * 16 + ch * 32;
                ldsm4(Bq[bp][0], ba);
                ldsm4(Bq[bp][1], ba + ATILE);
            }
            // products ordered prod-outer: same-acc distance 8
#pragma unroll
            for (int bp = 0; bp < 2; ++bp)
#pragma unroll
                for (int mf = 0; mf < 2; ++mf) {      // q0k0
                    hmma(S[mf][2 * bp + 0], A[0][mf], Bq[bp][0][0], Bq[bp][0][1]);
                    hmma(S[mf][2 * bp + 1], A[0][mf], Bq[bp][0][2], Bq[bp][0][3]);
                }
#pragma unroll
            for (int bp = 0; bp < 2; ++bp)
#pragma unroll
                for (int mf = 0; mf < 2; ++mf) {      // q0k1
                    hmma(S[mf][2 * bp + 0], A[0][mf], Bq[bp][1][0], Bq[bp][1][1]);
                    hmma(S[mf][2 * bp + 1], A[0][mf], Bq[bp][1][2], Bq[bp][1][3]);
                }
#pragma unroll
            for (int bp = 0; bp < 2; ++bp)
#pragma unroll
                for (int mf = 0; mf < 2; ++mf) {      // q1k0
                    hmma(S[mf][2 * bp + 0], A[1][mf], Bq[bp][0][0], Bq[bp][0][1]);
                    hmma(S[mf][2 * bp + 1], A[1][mf], Bq[bp][0][2], Bq[bp][0][3]);
                }
        }

        // ---- scale + mask + local max ----
        float mloc[4] = {-INFINITY, -INFINITY, -INFINITY, -INFINITY};
#pragma unroll
        for (int mf = 0; mf < 2; ++mf)
#pragma unroll
            for (int rh = 0; rh < 2; ++rh) {
                const int row = q0r + wm * 32 + mf * 16 + rh * 8 + rloc;
                const float* mrp = maskb + (size_t)row * SS + s * 128 + wn * 32
                                   + (lane & 3) * 2;
                const int sl = mf * 2 + rh;
#pragma unroll
                for (int nf = 0; nf < 4; ++nf) {
                    float2 mv = *(const float2*)(mrp + nf * 8);
                    float a = fmaf(S[mf][nf][rh * 2 + 0], scale, mv.x);
                    float c = fmaf(S[mf][nf][rh * 2 + 1], scale, mv.y);
                    S[mf][nf][rh * 2 + 0] = a;
                    S[mf][nf][rh * 2 + 1] = c;
                    mloc[sl] = fmaxf(mloc[sl], fmaxf(a, c));
                }
            }
#pragma unroll
        for (int off = 1; off < 4; off <<= 1)
#pragma unroll
            for (int sl = 0; sl < 4; ++sl)
                mloc[sl] = fmaxf(mloc[sl], __shfl_xor_sync(0xffffffffu, mloc[sl], off));

        // ---- exp with LOCAL max + local sum ----
        float lw[4];
#pragma unroll
        for (int mf = 0; mf < 2; ++mf)
#pragma unroll
            for (int rh = 0; rh < 2; ++rh) {
                const int sl = mf * 2 + rh;
                float ls = 0.0f;
#pragma unroll
                for (int nf = 0; nf < 4; ++nf) {
                    float a = __expf(S[mf][nf][rh * 2 + 0] - mloc[sl]);
                    float c = __expf(S[mf][nf][rh * 2 + 1] - mloc[sl]);
                    S[mf][nf][rh * 2 + 0] = a;
                    S[mf][nf][rh * 2 + 1] = c;
                    ls += a + c;
                }
                lw[sl] = ls;
            }
#pragma unroll
        for (int off = 1; off < 4; off <<= 1)
#pragma unroll
            for (int sl = 0; sl < 4; ++sl)
                lw[sl] += __shfl_xor_sync(0xffffffffu, lw[sl], off);

        if ((lane & 3) == 0) {
#pragma unroll
            for (int mf = 0; mf < 2; ++mf)
#pragma unroll
                for (int rh = 0; rh < 2; ++rh) {
                    const int rr = wm * 32 + mf * 16 + rh * 8 + rloc;
                    red[wn * 256 + rr * 2 + 0] = mloc[mf * 2 + rh];
                    red[wn * 256 + rr * 2 + 1] = lw[mf * 2 + rh];
                }
        }
        __syncthreads();                              // barrier B

        if (s + 2 < 16) {
            load_k(s + 2);
            asm volatile("cp.async.commit_group;" ::: "memory");
        }

        // ---- 4-quarter merge ----
        float alpha[4], beta[4];
#pragma unroll
        for (int mf = 0; mf < 2; ++mf)
#pragma unroll
            for (int rh = 0; rh < 2; ++rh) {
                const int sl = mf * 2 + rh;
                const int rr = wm * 32 + mf * 16 + rh * 8 + rloc;
                float mq[4], lq[4];
                float mnew = mst[sl];
#pragma unroll
                for (int q = 0; q < 4; ++q) {
                    mq[q] = red[q * 256 + rr * 2 + 0];
                    lq[q] = red[q * 256 + rr * 2 + 1];
                    mnew = fmaxf(mnew, mq[q]);
                }
                alpha[sl] = __expf(mst[sl] - mnew);
                float lacc = lst[sl] * alpha[sl];
#pragma unroll
                for (int q = 0; q < 4; ++q)
                    lacc += lq[q] * __expf(mq[q] - mnew);
                beta[sl] = __expf(mloc[sl] - mnew);
                lst[sl] = lacc;
                mst[sl] = mnew;
            }
#pragma unroll
        for (int mf = 0; mf < 2; ++mf)
#pragma unroll
            for (int dn = 0; dn < 8; ++dn) {
                O[mf][dn][0] *= alpha[mf * 2 + 0];
                O[mf][dn][1] *= alpha[mf * 2 + 0];
                O[mf][dn][2] *= alpha[mf * 2 + 1];
                O[mf][dn][3] *= alpha[mf * 2 + 1];
            }

        // ---- PV over this warp's 32 k-rows ----
#pragma unroll
        for (int kch = 0; kch < 2; ++kch) {
            uint32_t P0[2][4], P1[2][4];
#pragma unroll
            for (int mf = 0; mf < 2; ++mf) {
                const float b0s = beta[mf * 2 + 0];
                const float b1s = beta[mf * 2 + 1];
#pragma unroll
                for (int half = 0; half < 2; ++half) {
                    const float* c = S[mf][2 * kch + half];
                    float x0 = c[0] * b0s, x1 = c[1] * b0s;
                    float x2 = c[2] * b1s, x3 = c[3] * b1s;
                    __nv_bfloat162 t0 = __floats2bfloat162_rn(x0, x1);
                    __nv_bfloat162 t1 = __floats2bfloat162_rn(x2, x3);
                    __nv_bfloat162 u0 = __floats2bfloat162_rn(
                        x0 - __bfloat162float(t0.x), x1 - __bfloat162float(t0.y));
                    __nv_bfloat162 u1 = __floats2bfloat162_rn(
                        x2 - __bfloat162float(t1.x), x3 - __bfloat162float(t1.y));
                    P0[mf][half * 2 + 0] = *(uint32_t*)&t0;
                    P0[mf][half * 2 + 1] = *(uint32_t*)&t1;
                    P1[mf][half * 2 + 0] = *(uint32_t*)&u0;
                    P1[mf][half * 2 + 1] = *(uint32_t*)&u1;
                }
            }
            const uint32_t vrow = (uint32_t)(wn * 32 + kch * 16
                                  + ((lane >> 4) & 1) * 8 + (lane & 7)) * 144
                                  + ((lane >> 3) & 1) * 16;
#pragma unroll
            for (int dh = 0; dh < 2; ++dh) {
                uint32_t V[2][2][4];   // [dnp_local][limb]
#pragma unroll
                for (int dl = 0; dl < 2; ++dl) {
                    const uint32_t va = vst + vrow + (dh * 2 + dl) * 32;
                    ldsm4t(V[dl][0], va);
                    ldsm4t(V[dl][1], va + ATILE);
                }
                // prod-outer ordering: same-acc distance 8
#pragma unroll
                for (int dl = 0; dl < 2; ++dl)
#pragma unroll
                    for (int mf = 0; mf < 2; ++mf) {   // p0 v0
                        const int dn = 2 * (dh * 2 + dl);
                        hmma(O[mf][dn + 0], P0[mf], V[dl][0][0], V[dl][0][2]);
                        hmma(O[mf][dn + 1], P0[mf], V[dl][0][1], V[dl][0][3]);
                    }
#pragma unroll
                for (int dl = 0; dl < 2; ++dl)
#pragma unroll
                    for (int mf = 0; mf < 2; ++mf) {   // p0 v1
                        const int dn = 2 * (dh * 2 + dl);
                        hmma(O[mf][dn + 0], P0[mf], V[dl][1][0], V[dl][1][2]);
                        hmma(O[mf][dn + 1], P0[mf], V[dl][1][1], V[dl][1][3]);
                    }
#pragma unroll
                for (int dl = 0; dl < 2; ++dl)
#pragma unroll
                    for (int mf = 0; mf < 2; ++mf) {   // p1 v0
                        const int dn = 2 * (dh * 2 + dl);
                        hmma(O[mf][dn + 0], P1[mf], V[dl][0][0], V[dl][0][2]);
                        hmma(O[mf][dn + 1], P1[mf], V[dl][0][1], V[dl][0][3]);
                    }
            }
        }
    }

    // ---- epilogue: 4-phase O reduction across wn, normalize, limb store ----
    __syncthreads();
    float* osm = (float*)smem;     // [128][64]
#pragma unroll
    for (int phase = 3; phase >= 1; --phase) {
        if (wn == phase) {
#pragma unroll
            for (int mf = 0; mf < 2; ++mf)
#pragma unroll
                for (int rh = 0; rh < 2; ++rh) {
                    const int row = wm * 32 + mf * 16 + rh * 8 + rloc;
#pragma unroll
                    for (int dn = 0; dn < 8; ++dn) {
                        const int col = dn * 8 + (lane & 3) * 2;
                        float x = O[mf][dn][rh * 2 + 0];
                        float y = O[mf][dn][rh * 2 + 1];
                        if (phase != 3) {
                            float2 prev = *(float2*)(osm + row * 64 + col);
                            x += prev.x; y += prev.y;
                        }
                        *(float2*)(osm + row * 64 + col) = make_float2(x, y);
                    }
                }
        }
        __syncthreads();
    }
    if (wn == 0) {
#pragma unroll
        for (int mf = 0; mf < 2; ++mf)
#pragma unroll
            for (int rh = 0; rh < 2; ++rh) {
                const int sl  = mf * 2 + rh;
                const int row = wm * 32 + mf * 16 + rh * 8 + rloc;
                const float inv = 1.0f / lst[sl];
                const size_t obase = hb + (size_t)(q0r + row) * HH;
#pragma unroll
                for (int dn = 0; dn < 8; ++dn) {
                    const int col = dn * 8 + (lane & 3) * 2;
                    float2 ov = *(float2*)(osm + row * 64 + col);
                    float x = (O[mf][dn][rh * 2 + 0] + ov.x) * inv;
                    float y = (O[mf][dn][rh * 2 + 1] + ov.y) * inv;
                    __nv_bfloat162 h0 = __floats2bfloat162_rn(x, y);
                    __nv_bfloat162 g0 = __floats2bfloat162_rn(
                        x - __bfloat162float(h0.x), y - __bfloat162float(h0.y));
                    *(uint32_t*)(cx0 + obase + col) = *(uint32_t*)&h0;
                    *(uint32_t*)(cx1 + obase + col) = *(uint32_t*)&g0;
                }
            }
    }
}

// ---------------------------------------------------------------------------
// Launch
// ---------------------------------------------------------------------------
extern "C" void kernel_launch(void* const* d_in, const int* in_sizes, int n_in,
                              void* d_out, int out_size)
{
    const float* hs  = (const float*)d_in[0];
    const float* msk = (const float*)d_in[1];
    const float* q_s = (const float*)d_in[2];
    const float* q_d = (const float*)d_in[3];
    const float* k_s = (const float*)d_in[4];
    const float* k_d = (const float*)d_in[5];
    const float* v_s = (const float*)d_in[6];
    const float* v_d = (const float*)d_in[7];
    const float* o_s = (const float*)d_in[8];
    const float* o_d = (const float*)d_in[9];
    float* out = (float*)d_out;

    void* p;
    cudaGetSymbolAddress(&p, g_hs);  bf16* hsL = (bf16*)p;
    cudaGetSymbolAddress(&p, g_wsp); bf16* wsp = (bf16*)p;
    cudaGetSymbolAddress(&p, g_qkv); bf16* qkv = (bf16*)p;
    cudaGetSymbolAddress(&p, g_cx);  bf16* cxL = (bf16*)p;

    const size_t AE = (size_t)MM * HH;
    const size_t WE = (size_t)HH * HH;
    bf16 *hs0 = hsL, *hs1 = hsL + AE, *hs2 = hsL + 2 * AE;
    bf16 *wq0 = wsp,          *wq1 = wsp + WE,      *wq2 = wsp + 2 * WE;
    bf16 *wk0 = wsp + 3 * WE, *wk1 = wsp + 4 * WE,  *wk2 = wsp + 5 * WE;
    bf16 *wv0 = wsp + 6 * WE, *wv1 = wsp + 7 * WE,  *wv2 = wsp + 8 * WE;
    bf16 *wo0 = wsp + 9 * WE, *wo1 = wsp + 10 * WE, *wo2 = wsp + 11 * WE;
    bf16 *pq0 = qkv,          *pq1 = qkv + AE;
    bf16 *pk0 = qkv + 2 * AE, *pk1 = qkv + 3 * AE;
    bf16 *pv0 = qkv + 4 * AE, *pv1 = qkv + 5 * AE;
    bf16 *cx0 = cxL,          *cx1 = cxL + AE;

    // Splits
    split_hs<<<(int)(AE / 4 / 256), 256>>>((const float4*)hs, hs0, hs1, hs2,
                                           (int)(AE / 4));
    WSplitArgs wa;
    wa.a[0] = (const float4*)q_s; wa.b[0] = (const float4*)q_d;
    wa.l0[0] = wq0; wa.l1[0] = wq1; wa.l2[0] = wq2;
    wa.a[1] = (const float4*)k_s; wa.b[1] = (const float4*)k_d;
    wa.l0[1] = wk0; wa.l1[1] = wk1; wa.l2[1] = wk2;
    wa.a[2] = (const float4*)v_s; wa.b[2] = (const float4*)v_d;
    wa.l0[2] = wv0; wa.l1[2] = wv1; wa.l2[2] = wv2;
    wa.a[3] = (const float4*)o_s; wa.b[3] = (const float4*)o_d;
    wa.l0[3] = wo0; wa.l1[3] = wo1; wa.l2[3] = wo2;
    split_w4<<<dim3((int)(WE / 4 / 256), 4), 256>>>(wa, (int)(WE / 4));

    // GEMMs: swizzled 2-stage, 2 CTAs/SM
    const int SMEM3 = 2 * 6 * 8192;   // 98304
    const int SMEM2 = 2 * 4 * 8192;   // 65536
    cudaFuncSetAttribute(mma_gemm<3, true>,  cudaFuncAttributeMaxDynamicSharedMemorySize, SMEM3);
    cudaFuncSetAttribute(mma_gemm<2, true>,  cudaFuncAttributeMaxDynamicSharedMemorySize, SMEM2);
    cudaFuncSetAttribute(mma_gemm<2, false>, cudaFuncAttributeMaxDynamicSharedMemorySize, SMEM2);
    dim3 gg(HH / 128, MM / 128);

    mma_gemm<3, true><<<gg, 256, SMEM3>>>(hs0, hs1, hs2, wq0, wq1, wq2,
                                          nullptr, pq0, pq1);
    mma_gemm<3, true><<<gg, 256, SMEM3>>>(hs0, hs1, hs2, wk0, wk1, wk2,
                                          nullptr, pk0, pk1);
    mma_gemm<2, true><<<gg, 256, SMEM2>>>(hs0, hs1, nullptr, wv0, wv1, nullptr,
                                          nullptr, pv0, pv1);

    // Attention: 512 threads, 16 warps
    const int attn_smem = 4 * KSTAGE + 2 * ATILE + 4096;   // 188416
    cudaFuncSetAttribute(attn_mma, cudaFuncAttributeMaxDynamicSharedMemorySize,
                         attn_smem);
    dim3 agrid(SS / 128, NHH, BB);
    attn_mma<<<agrid, 512, attn_smem>>>(pq0, pq1, pk0, pk1, pv0, pv1, msk,
                                        cx0, cx1);

    // O projection
    mma_gemm<2, false><<<gg, 256, SMEM2>>>(cx0, cx1, nullptr, wo0, wo1, nullptr,
                                           out, nullptr, nullptr);
}